// round 11
// baseline (speedup 1.0000x reference)
#include <cuda_runtime.h>
#include <math.h>
#include <stdint.h>

// Problem constants
#define BB  8
#define SS  1024
#define DD  768
#define EE  24
#define DHH 128
#define DFF 384
#define NN  6144          // S*H tokens per batch
#define KK  1024          // tokens per expert
#define HH  6             // heads

// ---------------- scratch (device globals; no allocation allowed) -----------
__device__ float g_x1[(size_t)BB * NN * DHH];     // head-projected tokens
__device__ float g_gates[(size_t)BB * EE * NN];
__device__ int   g_idx[(size_t)BB * EE * KK];
__device__ float g_gateval[(size_t)BB * EE * KK];
__device__ float g_xout[(size_t)BB * NN * DHH];   // scatter accumulator (fp32)
__device__ float g_W[DD * HH * EE];               // fused gating matrix [768][144]
__device__ float g_w1r[(size_t)EE * DHH * DFF];   // w1 rounded to tf32
__device__ float g_w2r[(size_t)EE * DFF * DHH];   // w2 rounded to tf32
__device__ float g_xr[(size_t)BB * SS * DD];      // rna(x)
__device__ float g_hr[DD * DD];                   // rna(head)
__device__ float g_mr[DD * DD];                   // rna(merge)
__device__ float g_xor[(size_t)BB * NN * DHH];    // rna(xout)

// ---------------- helpers ----------------------------------------------------
__device__ __forceinline__ float f_rna(float x) {
    uint32_t u;
    asm("cvt.rna.tf32.f32 %0, %1;" : "=r"(u) : "f"(x));
    return __uint_as_float(u);
}

__device__ __forceinline__ void mma8(float* c, const uint32_t* a, const uint32_t* b) {
    asm volatile(
        "mma.sync.aligned.m16n8k8.row.col.f32.tf32.tf32.f32 "
        "{%0,%1,%2,%3}, {%4,%5,%6,%7}, {%8,%9}, {%0,%1,%2,%3};\n"
        : "+f"(c[0]), "+f"(c[1]), "+f"(c[2]), "+f"(c[3])
        : "r"(a[0]), "r"(a[1]), "r"(a[2]), "r"(a[3]), "r"(b[0]), "r"(b[1]));
}

__device__ __forceinline__ void cp16(void* smem, const void* g) {
    uint32_t s = (uint32_t)__cvta_generic_to_shared(smem);
    asm volatile("cp.async.ca.shared.global [%0], [%1], 16;" :: "r"(s), "l"(g));
}
#define CP_COMMIT asm volatile("cp.async.commit_group;")
#define CP_WAIT0  asm volatile("cp.async.wait_group 0;")
#define CP_WAIT1  asm volatile("cp.async.wait_group 1;")

// ---------------- elementwise tf32 round -------------------------------------
__global__ void round_tf32_kernel(const float* __restrict__ src,
                                  float* __restrict__ dst, size_t n) {
    size_t i = ((size_t)blockIdx.x * blockDim.x + threadIdx.x) * 4;
    if (i >= n) return;
    float4 v = *(const float4*)(src + i);
    v.x = f_rna(v.x); v.y = f_rna(v.y); v.z = f_rna(v.z); v.w = f_rna(v.w);
    *(float4*)(dst + i) = v;
}

// ---------------- fused gating matrix: W[d][h*24+e] --------------------------
__global__ __launch_bounds__(144) void choice_proj_kernel(
    const float* __restrict__ head, const float* __restrict__ choice)
{
    __shared__ float hs[DD];
    __shared__ float cs[EE * DHH];
    const int d = blockIdx.x;
    for (int i = threadIdx.x; i < DD; i += 144) hs[i] = head[(size_t)d * DD + i];
    for (int i = threadIdx.x; i < EE * DHH; i += 144) cs[i] = choice[i];
    __syncthreads();
    const int h = threadIdx.x / EE, e = threadIdx.x % EE;
    float a = 0.f;
#pragma unroll 8
    for (int o = 0; o < DHH; o++) a += hs[h * DHH + o] * cs[e * DHH + o];
    g_W[d * (HH * EE) + threadIdx.x] = a;
}

// ---------------- logits (fp32 SIMT GEMM) + softmax --------------------------
#define LG_XS 0
#define LG_WS 2112
#define LG_LS (2112 + 4640)
#define LG_SMEM_BYTES ((2112 + 4640 + 64 * 145) * 4)

__global__ __launch_bounds__(384) void logits_softmax_kernel(const float* __restrict__ x) {
    extern __shared__ float sm[];
    float* Xs = sm + LG_XS;   // [64][33]
    float* Ws = sm + LG_WS;   // [32][145]
    float* Ls = sm + LG_LS;   // [64][145]
    const int tid = threadIdx.x;
    const int row0 = blockIdx.x * 64;
    const int ry = tid / 24, cx = tid % 24;

    float acc[4][6];
#pragma unroll
    for (int i = 0; i < 4; i++)
#pragma unroll
        for (int j = 0; j < 6; j++) acc[i][j] = 0.f;

    for (int k0 = 0; k0 < DD; k0 += 32) {
        for (int i = tid; i < 64 * 32; i += 384) {
            int r = i >> 5, c = i & 31;
            Xs[r * 33 + c] = x[(size_t)(row0 + r) * DD + k0 + c];
        }
        for (int i = tid; i < 32 * 144; i += 384) {
            int r = i / 144, c = i % 144;
            Ws[r * 145 + c] = g_W[(k0 + r) * 144 + c];
        }
        __syncthreads();
#pragma unroll 8
        for (int kk = 0; kk < 32; kk++) {
            float xv[4], wv[6];
#pragma unroll
            for (int i = 0; i < 4; i++) xv[i] = Xs[(ry * 4 + i) * 33 + kk];
#pragma unroll
            for (int j = 0; j < 6; j++) wv[j] = Ws[kk * 145 + cx * 6 + j];
#pragma unroll
            for (int i = 0; i < 4; i++)
#pragma unroll
                for (int j = 0; j < 6; j++) acc[i][j] += xv[i] * wv[j];
        }
        __syncthreads();
    }
#pragma unroll
    for (int i = 0; i < 4; i++)
#pragma unroll
        for (int j = 0; j < 6; j++)
            Ls[(ry * 4 + i) * 145 + cx * 6 + j] = acc[i][j];
    __syncthreads();

    {
        const int r = tid / 6, h = tid % 6;
        const int row = row0 + r;
        const int b = row / SS, s = row % SS;
        const int n = s * HH + h;
        float l[EE];
        float m = -1e30f;
#pragma unroll
        for (int e = 0; e < EE; e++) {
            l[e] = Ls[r * 145 + h * EE + e];
            m = fmaxf(m, l[e]);
        }
        float sum = 0.f;
#pragma unroll
        for (int e = 0; e < EE; e++) { l[e] = expf(l[e] - m); sum += l[e]; }
        const float inv = 1.f / sum;
#pragma unroll
        for (int e = 0; e < EE; e++)
            g_gates[((size_t)(b * EE + e)) * NN + n] = l[e] * inv;
    }
}

// ---------------- 64x64-warp tf32 GEMM (head + merge proj) -------------------
// 128x128 block, 128 threads / 4 warps (warp 64x64), cp.async double buffer,
// operands pre-rounded to tf32 in global. 70KB smem -> 2 CTAs/SM.
#define SA 36
#define SB 136
#define MG_A (128 * SA)
#define MG_B (32 * SB)
#define MG_BUF (MG_A + MG_B)
#define MG_SMEM_BYTES (2 * MG_BUF * 4)

__global__ __launch_bounds__(128, 2) void gemm64_kernel(
    const float* __restrict__ A, const float* __restrict__ B,
    float* __restrict__ C, int M, int N, int K)
{
    extern __shared__ float sm[];
    const int tid = threadIdx.x;
    const int bm = blockIdx.y * 128, bn = blockIdx.x * 128;

    const int warp = tid >> 5, lane = tid & 31;
    const int wm = (warp >> 1) * 64, wn = (warp & 1) * 64;
    const int ly = lane >> 2, lx = lane & 3;

    const int br = tid & 31, bseg = tid >> 5;   // B staging: row, 32-float seg

    const int T = K / 32;

    auto stage = [&](int buf, int kt) {
        float* base = sm + buf * MG_BUF;
        // A: 128 rows x 32 k, one row per thread
        float* ad = base + tid * SA;
        const float* as = A + (size_t)(bm + tid) * K + kt * 32;
#pragma unroll
        for (int j = 0; j < 32; j += 4) cp16(ad + j, as + j);
        // B: 32 rows x 128 n, row = lane, 32-col seg per warp
        float* bd = base + MG_A + br * SB + bseg * 32;
        const float* bs = B + (size_t)(kt * 32 + br) * N + bn + bseg * 32;
#pragma unroll
        for (int j = 0; j < 32; j += 4) cp16(bd + j, bs + j);
    };

    float c[4][8][4];
#pragma unroll
    for (int i = 0; i < 4; i++)
#pragma unroll
        for (int j = 0; j < 8; j++)
#pragma unroll
            for (int k = 0; k < 4; k++) c[i][j][k] = 0.f;

    stage(0, 0);
    CP_COMMIT;

    for (int t = 0; t < T; t++) {
        if (t + 1 < T) { stage((t + 1) & 1, t + 1); CP_COMMIT; CP_WAIT1; }
        else           { CP_WAIT0; }
        __syncthreads();
        const float* base = sm + (t & 1) * MG_BUF;
        const float* As = base;
        const float* Bs = base + MG_A;
#pragma unroll
        for (int ks = 0; ks < 4; ks++) {
            const int k0 = ks * 8;
            uint32_t a[4][4], bf[8][2];
#pragma unroll
            for (int am = 0; am < 4; am++) {
                const int off = (wm + am * 16 + ly) * SA + k0 + lx;
                a[am][0] = __float_as_uint(As[off]);
                a[am][1] = __float_as_uint(As[off + 8 * SA]);
                a[am][2] = __float_as_uint(As[off + 4]);
                a[am][3] = __float_as_uint(As[off + 8 * SA + 4]);
            }
#pragma unroll
            for (int an = 0; an < 8; an++) {
                const int off = (k0 + lx) * SB + wn + an * 8 + ly;
                bf[an][0] = __float_as_uint(Bs[off]);
                bf[an][1] = __float_as_uint(Bs[off + 4 * SB]);
            }
#pragma unroll
            for (int am = 0; am < 4; am++)
#pragma unroll
                for (int an = 0; an < 8; an++) mma8(c[am][an], a[am], bf[an]);
        }
        __syncthreads();
    }

#pragma unroll
    for (int am = 0; am < 4; am++) {
        const int row = bm + wm + am * 16 + ly;
#pragma unroll
        for (int an = 0; an < 8; an++) {
            const int col = bn + wn + an * 8 + 2 * lx;
            *(float2*)(C + (size_t)row * N + col)       = make_float2(c[am][an][0], c[am][an][1]);
            *(float2*)(C + (size_t)(row + 8) * N + col) = make_float2(c[am][an][2], c[am][an][3]);
        }
    }
}

// ---------------- deterministic top-K per (b,e) ------------------------------
__global__ __launch_bounds__(256) void topk_kernel() {
    __shared__ unsigned sv[NN];
    __shared__ int red[256];
    __shared__ int cnts[256];
    __shared__ int gtoff[256];
    __shared__ int eqoff[256];
    __shared__ int tot_gt;

    const int be = blockIdx.x;
    const int tid = threadIdx.x;
    const float* g = g_gates + (size_t)be * NN;
    for (int i = tid; i < NN; i += 256) sv[i] = __float_as_uint(g[i]);
    __syncthreads();

    unsigned thr = 0u;
    for (int bit = 30; bit >= 0; bit--) {
        unsigned cand = thr | (1u << bit);
        int c = 0;
        for (int i = tid; i < NN; i += 256) c += (sv[i] >= cand) ? 1 : 0;
        red[tid] = c;
        __syncthreads();
        for (int s = 128; s > 0; s >>= 1) {
            if (tid < s) red[tid] += red[tid + s];
            __syncthreads();
        }
        int tot = red[0];
        __syncthreads();
        if (tot >= KK) thr = cand;
    }

    const int base = tid * (NN / 256);
    int lgt = 0, leq = 0;
#pragma unroll
    for (int j = 0; j < NN / 256; j++) {
        unsigned v = sv[base + j];
        lgt += (v > thr);
        leq += (v == thr);
    }
    red[tid] = lgt;
    cnts[tid] = leq;
    __syncthreads();
    if (tid == 0) {
        int a = 0;
        for (int i = 0; i < 256; i++) { gtoff[i] = a; a += red[i]; }
        tot_gt = a;
        a = 0;
        for (int i = 0; i < 256; i++) { eqoff[i] = a; a += cnts[i]; }
    }
    __syncthreads();

    const int ngt = tot_gt;
    int pgt = gtoff[tid];
    int peq = ngt + eqoff[tid];
    int*   ip = g_idx     + (size_t)be * KK;
    float* gp = g_gateval + (size_t)be * KK;
#pragma unroll
    for (int j = 0; j < NN / 256; j++) {
        unsigned v = sv[base + j];
        if (v > thr) {
            ip[pgt] = base + j;
            gp[pgt] = __uint_as_float(v);
            pgt++;
        } else if (v == thr) {
            if (peq < KK) {
                ip[peq] = base + j;
                gp[peq] = __uint_as_float(v);
            }
            peq++;
        }
    }
}

// ---------------- zero accumulator ------------------------------------------
__global__ void zero_kernel() {
    size_t i = ((size_t)blockIdx.x * blockDim.x + threadIdx.x) * 4;
    if (i < (size_t)BB * NN * DHH) {
        *(float4*)(g_xout + i) = make_float4(0.f, 0.f, 0.f, 0.f);
    }
}

// ---------------- fused gather -> FFN (tf32 mma) -> gated scatter ------------
// block = (token_tile 128, expert, batch), 512 threads, 16 warps (warp 32x32).
#define FS_X 132
#define FS_W 136
#define FFN_XS   (128 * FS_X)
#define FFN_WS   (128 * FS_W)
#define FFN_SMEM_FLOATS (2 * FFN_XS + FFN_WS + 256)
#define FFN_SMEM_BYTES (FFN_SMEM_FLOATS * 4)

__global__ __launch_bounds__(512, 1) void ffn_tf32_kernel(const float* __restrict__ w1r,
                                                          const float* __restrict__ w2r) {
    extern __shared__ float sm[];
    float* Xs = sm;
    float* Hs = sm + FFN_XS;
    float* Ws = sm + 2 * FFN_XS;
    int*   toks = (int*)(sm + 2 * FFN_XS + FFN_WS);
    float* Gs   = sm + 2 * FFN_XS + FFN_WS + 128;

    const int tile = blockIdx.x, e = blockIdx.y, b = blockIdx.z;
    const int tid = threadIdx.x;
    const int be = b * EE + e;
    const int* idxp = g_idx + (size_t)be * KK + tile * 128;
    const float* gvp = g_gateval + (size_t)be * KK + tile * 128;
    const float* w1e = w1r + (size_t)e * DHH * DFF;
    const float* w2e = w2r + (size_t)e * DFF * DHH;

    const int row = tid >> 2, seg = tid & 3;

    {
        float* wd = Ws + row * FS_W + seg * 32;
        const float* wsrc = w1e + (size_t)row * DFF + seg * 32;
#pragma unroll
        for (int j = 0; j < 32; j += 4) cp16(wd + j, wsrc + j);
    }
    CP_COMMIT;

    {
        const int tok = idxp[row];
        if (seg == 0) { toks[row] = tok; Gs[row] = gvp[row]; }
        const float* xr = g_x1 + ((size_t)b * NN + tok) * DHH + seg * 32;
        float* xd = Xs + row * FS_X + seg * 32;
#pragma unroll
        for (int j = 0; j < 32; j += 4) {
            float4 v = *(const float4*)(xr + j);
            xd[j]     = f_rna(v.x);
            xd[j + 1] = f_rna(v.y);
            xd[j + 2] = f_rna(v.z);
            xd[j + 3] = f_rna(v.w);
        }
    }

    const int warp = tid >> 5, lane = tid & 31;
    const int wm = (warp >> 2) * 32, wn = (warp & 3) * 32;
    const int ly = lane >> 2, lx = lane & 3;

    float yacc[2][4][4];
#pragma unroll
    for (int i = 0; i < 2; i++)
#pragma unroll
        for (int j = 0; j < 4; j++)
#pragma unroll
            for (int k = 0; k < 4; k++) yacc[i][j][k] = 0.f;

    for (int c = 0; c < 3; c++) {
        CP_WAIT0;
        __syncthreads();

        float h[2][4][4];
#pragma unroll
        for (int i = 0; i < 2; i++)
#pragma unroll
            for (int j = 0; j < 4; j++)
#pragma unroll
                for (int k = 0; k < 4; k++) h[i][j][k] = 0.f;

#pragma unroll 4
        for (int ks = 0; ks < 16; ks++) {
            const int k0 = ks * 8;
            uint32_t a[2][4], bf[4][2];
#pragma unroll
            for (int am = 0; am < 2; am++) {
                const int off = (wm + am * 16 + ly) * FS_X + k0 + lx;
                a[am][0] = __float_as_uint(Xs[off]);
                a[am][1] = __float_as_uint(Xs[off + 8 * FS_X]);
                a[am][2] = __float_as_uint(Xs[off + 4]);
                a[am][3] = __float_as_uint(Xs[off + 8 * FS_X + 4]);
            }
#pragma unroll
            for (int an = 0; an < 4; an++) {
                const int off = (k0 + lx) * FS_W + wn + an * 8 + ly;
                bf[an][0] = __float_as_uint(Ws[off]);
                bf[an][1] = __float_as_uint(Ws[off + 4 * FS_W]);
            }
#pragma unroll
            for (int am = 0; am < 2; am++)
#pragma unroll
                for (int an = 0; an < 4; an++) mma8(h[am][an], a[am], bf[an]);
        }
        __syncthreads();

        {
            float* wd = Ws + row * FS_W + seg * 32;
            const float* wsrc = w2e + (size_t)(c * 128 + row) * DHH + seg * 32;
#pragma unroll
            for (int j = 0; j < 32; j += 4) cp16(wd + j, wsrc + j);
        }
        CP_COMMIT;

#pragma unroll
        for (int am = 0; am < 2; am++) {
            const int r0 = wm + am * 16 + ly;
#pragma unroll
            for (int an = 0; an < 4; an++) {
                const int col = wn + an * 8 + 2 * lx;
                float v0 = h[am][an][0], v1 = h[am][an][1];
                float v2 = h[am][an][2], v3 = h[am][an][3];
                v0 = v0 / (1.f + expf(-v0));
                v1 = v1 / (1.f + expf(-v1));
                v2 = v2 / (1.f + expf(-v2));
                v3 = v3 / (1.f + expf(-v3));
                *(float2*)&Hs[r0 * FS_X + col]       = make_float2(f_rna(v0), f_rna(v1));
                *(float2*)&Hs[(r0 + 8) * FS_X + col] = make_float2(f_rna(v2), f_rna(v3));
            }
        }
        CP_WAIT0;
        __syncthreads();

#pragma unroll 4
        for (int ks = 0; ks < 16; ks++) {
            const int k0 = ks * 8;
            uint32_t a[2][4], bf[4][2];
#pragma unroll
            for (int am = 0; am < 2; am++) {
                const int off = (wm + am * 16 + ly) * FS_X + k0 + lx;
                a[am][0] = __float_as_uint(Hs[off]);
                a[am][1] = __float_as_uint(Hs[off + 8 * FS_X]);
                a[am][2] = __float_as_uint(Hs[off + 4]);
                a[am][3] = __float_as_uint(Hs[off + 8 * FS_X + 4]);
            }
#pragma unroll
            for (int an = 0; an < 4; an++) {
                const int off = (k0 + lx) * FS_W + wn + an * 8 + ly;
                bf[an][0] = __float_as_uint(Ws[off]);
                bf[an][1] = __float_as_uint(Ws[off + 4 * FS_W]);
            }
#pragma unroll
            for (int am = 0; am < 2; am++)
#pragma unroll
                for (int an = 0; an < 4; an++) mma8(yacc[am][an], a[am], bf[an]);
        }
        __syncthreads();

        if (c < 2) {
            float* wd = Ws + row * FS_W + seg * 32;
            const float* wsrc = w1e + (size_t)row * DFF + (c + 1) * 128 + seg * 32;
#pragma unroll
            for (int j = 0; j < 32; j += 4) cp16(wd + j, wsrc + j);
            CP_COMMIT;
        }
    }

#pragma unroll
    for (int am = 0; am < 2; am++) {
        const int r0 = wm + am * 16 + ly;
        const int tok0 = toks[r0], tok1 = toks[r0 + 8];
        const float g0 = Gs[r0], g1 = Gs[r0 + 8];
        float* o0 = g_xout + ((size_t)b * NN + tok0) * DHH;
        float* o1 = g_xout + ((size_t)b * NN + tok1) * DHH;
#pragma unroll
        for (int an = 0; an < 4; an++) {
            const int col = wn + an * 8 + 2 * lx;
            atomicAdd(o0 + col,     yacc[am][an][0] * g0);
            atomicAdd(o0 + col + 1, yacc[am][an][1] * g0);
            atomicAdd(o1 + col,     yacc[am][an][2] * g1);
            atomicAdd(o1 + col + 1, yacc[am][an][3] * g1);
        }
    }
}

// ---------------- launch ----------------------------------------------------
extern "C" void kernel_launch(void* const* d_in, const int* in_sizes, int n_in,
                              void* d_out, int out_size) {
    const float* x      = (const float*)d_in[0];
    const float* choice = (const float*)d_in[1];
    const float* w1     = (const float*)d_in[2];
    const float* w2     = (const float*)d_in[3];
    const float* head   = (const float*)d_in[4];
    const float* merge  = (const float*)d_in[5];
    float* out = (float*)d_out;

    float *x1p, *xop, *w1r, *w2r, *xr, *hr, *mr, *xorp;
    cudaGetSymbolAddress((void**)&x1p, g_x1);
    cudaGetSymbolAddress((void**)&xop, g_xout);
    cudaGetSymbolAddress((void**)&w1r, g_w1r);
    cudaGetSymbolAddress((void**)&w2r, g_w2r);
    cudaGetSymbolAddress((void**)&xr, g_xr);
    cudaGetSymbolAddress((void**)&hr, g_hr);
    cudaGetSymbolAddress((void**)&mr, g_mr);
    cudaGetSymbolAddress((void**)&xorp, g_xor);

    cudaFuncSetAttribute(gemm64_kernel, cudaFuncAttributeMaxDynamicSharedMemorySize,
                         MG_SMEM_BYTES);
    cudaFuncSetAttribute(ffn_tf32_kernel, cudaFuncAttributeMaxDynamicSharedMemorySize,
                         FFN_SMEM_BYTES);
    cudaFuncSetAttribute(logits_softmax_kernel, cudaFuncAttributeMaxDynamicSharedMemorySize,
                         LG_SMEM_BYTES);

    const size_t nX = (size_t)BB * SS * DD;     // 6291456
    const size_t nW = (size_t)DD * DD;          // 589824
    const size_t nW1 = (size_t)EE * DHH * DFF;  // 1179648

    // 0) fused gating matrix W = head_slices @ choice^T (exact fp32)
    choice_proj_kernel<<<DD, 144>>>(head, choice);

    // tf32 pre-rounds
    round_tf32_kernel<<<(unsigned)(nX / 1024), 256>>>(x, xr, nX);
    round_tf32_kernel<<<(unsigned)(nW / 1024), 256>>>(head, hr, nW);
    round_tf32_kernel<<<(unsigned)(nW / 1024), 256>>>(merge, mr, nW);
    round_tf32_kernel<<<(unsigned)(nW1 / 1024), 256>>>(w1, w1r, nW1);
    round_tf32_kernel<<<(unsigned)(nW1 / 1024), 256>>>(w2, w2r, nW1);

    // 1) head projection (tf32 tensor, 64x64 warps)
    dim3 gproj(DD / 128, (BB * SS) / 128);
    gemm64_kernel<<<gproj, 128, MG_SMEM_BYTES>>>(xr, hr, x1p, BB * SS, DD, DD);

    // 2) exact-fp32 logits + softmax (independent of x1 accuracy)
    logits_softmax_kernel<<<(BB * SS) / 64, 384, LG_SMEM_BYTES>>>(x);

    // 3) per-(b,e) top-K
    topk_kernel<<<BB * EE, 256>>>();

    // 4) zero accumulator
    zero_kernel<<<(BB * NN * DHH) / (256 * 4), 256>>>();

    // 5) fused gather -> FFN (tf32 tensor) -> gated scatter
    dim3 gffn(KK / 128, EE, BB);
    ffn_tf32_kernel<<<gffn, 512, FFN_SMEM_BYTES>>>(w1r, w2r);

    // 6) merge projection (round xout, then tf32 tensor GEMM)
    round_tf32_kernel<<<(unsigned)(nX / 1024), 256>>>(xop, xorp, nX);
    gemm64_kernel<<<gproj, 128, MG_SMEM_BYTES>>>(xorp, mr, out, BB * SS, DD, DD);
}

// round 12
// speedup vs baseline: 1.0401x; 1.0401x over previous
#include <cuda_runtime.h>
#include <math.h>
#include <stdint.h>

// Problem constants
#define BB  8
#define SS  1024
#define DD  768
#define EE  24
#define DHH 128
#define DFF 384
#define NN  6144          // S*H tokens per batch
#define KK  1024          // tokens per expert
#define HH  6             // heads

// ---------------- scratch (device globals; no allocation allowed) -----------
__device__ float g_x1[(size_t)BB * NN * DHH];     // head-projected tokens
__device__ float g_gates[(size_t)BB * EE * NN];
__device__ int   g_idx[(size_t)BB * EE * KK];
__device__ float g_gateval[(size_t)BB * EE * KK];
__device__ float g_xout[(size_t)BB * NN * DHH];   // scatter accumulator (fp32)
__device__ float g_W[DD * HH * EE];               // fused gating matrix [768][144]
__device__ float g_w1r[(size_t)EE * DHH * DFF];   // w1 rounded to tf32
__device__ float g_w2r[(size_t)EE * DFF * DHH];   // w2 rounded to tf32
__device__ float g_xr[(size_t)BB * SS * DD];      // rna(x)
__device__ float g_hr[DD * DD];                   // rna(head)
__device__ float g_mr[DD * DD];                   // rna(merge)
__device__ float g_xor[(size_t)BB * NN * DHH];    // rna(xout)

// ---------------- helpers ----------------------------------------------------
__device__ __forceinline__ float f_rna(float x) {
    uint32_t u;
    asm("cvt.rna.tf32.f32 %0, %1;" : "=r"(u) : "f"(x));
    return __uint_as_float(u);
}

__device__ __forceinline__ void mma8(float* c, const uint32_t* a, const uint32_t* b) {
    asm volatile(
        "mma.sync.aligned.m16n8k8.row.col.f32.tf32.tf32.f32 "
        "{%0,%1,%2,%3}, {%4,%5,%6,%7}, {%8,%9}, {%0,%1,%2,%3};\n"
        : "+f"(c[0]), "+f"(c[1]), "+f"(c[2]), "+f"(c[3])
        : "r"(a[0]), "r"(a[1]), "r"(a[2]), "r"(a[3]), "r"(b[0]), "r"(b[1]));
}

__device__ __forceinline__ void cp16(void* smem, const void* g) {
    uint32_t s = (uint32_t)__cvta_generic_to_shared(smem);
    asm volatile("cp.async.ca.shared.global [%0], [%1], 16;" :: "r"(s), "l"(g));
}
#define CP_COMMIT asm volatile("cp.async.commit_group;")
#define CP_WAIT0  asm volatile("cp.async.wait_group 0;")
#define CP_WAIT1  asm volatile("cp.async.wait_group 1;")

// ---------------- elementwise tf32 round -------------------------------------
__global__ void round_tf32_kernel(const float* __restrict__ src,
                                  float* __restrict__ dst, size_t n) {
    size_t i = ((size_t)blockIdx.x * blockDim.x + threadIdx.x) * 4;
    if (i >= n) return;
    float4 v = *(const float4*)(src + i);
    v.x = f_rna(v.x); v.y = f_rna(v.y); v.z = f_rna(v.z); v.w = f_rna(v.w);
    *(float4*)(dst + i) = v;
}

// ---------------- fused gating matrix: W[d][h*24+e] --------------------------
__global__ __launch_bounds__(144) void choice_proj_kernel(
    const float* __restrict__ head, const float* __restrict__ choice)
{
    __shared__ float hs[DD];
    __shared__ float cs[EE * DHH];
    const int d = blockIdx.x;
    for (int i = threadIdx.x; i < DD; i += 144) hs[i] = head[(size_t)d * DD + i];
    for (int i = threadIdx.x; i < EE * DHH; i += 144) cs[i] = choice[i];
    __syncthreads();
    const int h = threadIdx.x / EE, e = threadIdx.x % EE;
    float a = 0.f;
#pragma unroll 8
    for (int o = 0; o < DHH; o++) a += hs[h * DHH + o] * cs[e * DHH + o];
    g_W[d * (HH * EE) + threadIdx.x] = a;
}

// ---------------- logits (fp32 SIMT GEMM) + softmax --------------------------
#define LG_XS 0
#define LG_WS 2112
#define LG_LS (2112 + 4640)
#define LG_SMEM_BYTES ((2112 + 4640 + 64 * 145) * 4)

__global__ __launch_bounds__(384) void logits_softmax_kernel(const float* __restrict__ x) {
    extern __shared__ float sm[];
    float* Xs = sm + LG_XS;   // [64][33]
    float* Ws = sm + LG_WS;   // [32][145]
    float* Ls = sm + LG_LS;   // [64][145]
    const int tid = threadIdx.x;
    const int row0 = blockIdx.x * 64;
    const int ry = tid / 24, cx = tid % 24;

    float acc[4][6];
#pragma unroll
    for (int i = 0; i < 4; i++)
#pragma unroll
        for (int j = 0; j < 6; j++) acc[i][j] = 0.f;

    for (int k0 = 0; k0 < DD; k0 += 32) {
        for (int i = tid; i < 64 * 32; i += 384) {
            int r = i >> 5, c = i & 31;
            Xs[r * 33 + c] = x[(size_t)(row0 + r) * DD + k0 + c];
        }
        for (int i = tid; i < 32 * 144; i += 384) {
            int r = i / 144, c = i % 144;
            Ws[r * 145 + c] = g_W[(k0 + r) * 144 + c];
        }
        __syncthreads();
#pragma unroll 8
        for (int kk = 0; kk < 32; kk++) {
            float xv[4], wv[6];
#pragma unroll
            for (int i = 0; i < 4; i++) xv[i] = Xs[(ry * 4 + i) * 33 + kk];
#pragma unroll
            for (int j = 0; j < 6; j++) wv[j] = Ws[kk * 145 + cx * 6 + j];
#pragma unroll
            for (int i = 0; i < 4; i++)
#pragma unroll
                for (int j = 0; j < 6; j++) acc[i][j] += xv[i] * wv[j];
        }
        __syncthreads();
    }
#pragma unroll
    for (int i = 0; i < 4; i++)
#pragma unroll
        for (int j = 0; j < 6; j++)
            Ls[(ry * 4 + i) * 145 + cx * 6 + j] = acc[i][j];
    __syncthreads();

    {
        const int r = tid / 6, h = tid % 6;
        const int row = row0 + r;
        const int b = row / SS, s = row % SS;
        const int n = s * HH + h;
        float l[EE];
        float m = -1e30f;
#pragma unroll
        for (int e = 0; e < EE; e++) {
            l[e] = Ls[r * 145 + h * EE + e];
            m = fmaxf(m, l[e]);
        }
        float sum = 0.f;
#pragma unroll
        for (int e = 0; e < EE; e++) { l[e] = expf(l[e] - m); sum += l[e]; }
        const float inv = 1.f / sum;
#pragma unroll
        for (int e = 0; e < EE; e++)
            g_gates[((size_t)(b * EE + e)) * NN + n] = l[e] * inv;
    }
}

// ---------------- tf32 GEMM (head + merge proj), cp.async staging ------------
// 128x128 block, 256 threads / 8 warps (warp 64x32), K-tile 32, cp.async
// double buffer, operands pre-rounded to tf32 in global. 70KB smem -> 2 CTAs/SM.
#define SA 36
#define SB 136
#define MG_A (128 * SA)
#define MG_B (32 * SB)
#define MG_BUF (MG_A + MG_B)
#define MG_SMEM_BYTES (2 * MG_BUF * 4)

__global__ __launch_bounds__(256, 2) void gemm_cp_kernel(
    const float* __restrict__ A, const float* __restrict__ B,
    float* __restrict__ C, int M, int N, int K)
{
    extern __shared__ float sm[];
    const int tid = threadIdx.x;
    const int bm = blockIdx.y * 128, bn = blockIdx.x * 128;

    const int ar = tid >> 1, ac0 = (tid & 1) * 16;   // A: 128 rows x 32 k
    const int br = tid >> 3, bc0 = (tid & 7) * 16;   // B: 32 rows x 128 n

    const int warp = tid >> 5, lane = tid & 31;
    const int wm = (warp >> 2) * 64, wn = (warp & 3) * 32;
    const int ly = lane >> 2, lx = lane & 3;

    const int T = K / 32;

    auto stage = [&](int buf, int kt) {
        float* base = sm + buf * MG_BUF;
        float* ad = base + ar * SA + ac0;
        const float* as = A + (size_t)(bm + ar) * K + kt * 32 + ac0;
#pragma unroll
        for (int j = 0; j < 16; j += 4) cp16(ad + j, as + j);
        float* bd = base + MG_A + br * SB + bc0;
        const float* bs = B + (size_t)(kt * 32 + br) * N + bn + bc0;
#pragma unroll
        for (int j = 0; j < 16; j += 4) cp16(bd + j, bs + j);
    };

    float c[4][4][4];
#pragma unroll
    for (int i = 0; i < 4; i++)
#pragma unroll
        for (int j = 0; j < 4; j++)
#pragma unroll
            for (int k = 0; k < 4; k++) c[i][j][k] = 0.f;

    stage(0, 0);
    CP_COMMIT;

    for (int t = 0; t < T; t++) {
        if (t + 1 < T) { stage((t + 1) & 1, t + 1); CP_COMMIT; CP_WAIT1; }
        else           { CP_WAIT0; }
        __syncthreads();
        const float* base = sm + (t & 1) * MG_BUF;
        const float* As = base;
        const float* Bs = base + MG_A;
#pragma unroll
        for (int ks = 0; ks < 4; ks++) {
            const int k0 = ks * 8;
            uint32_t a[4][4], bf[4][2];
#pragma unroll
            for (int am = 0; am < 4; am++) {
                const int off = (wm + am * 16 + ly) * SA + k0 + lx;
                a[am][0] = __float_as_uint(As[off]);
                a[am][1] = __float_as_uint(As[off + 8 * SA]);
                a[am][2] = __float_as_uint(As[off + 4]);
                a[am][3] = __float_as_uint(As[off + 8 * SA + 4]);
            }
#pragma unroll
            for (int an = 0; an < 4; an++) {
                const int off = (k0 + lx) * SB + wn + an * 8 + ly;
                bf[an][0] = __float_as_uint(Bs[off]);
                bf[an][1] = __float_as_uint(Bs[off + 4 * SB]);
            }
#pragma unroll
            for (int am = 0; am < 4; am++)
#pragma unroll
                for (int an = 0; an < 4; an++) mma8(c[am][an], a[am], bf[an]);
        }
        __syncthreads();
    }

#pragma unroll
    for (int am = 0; am < 4; am++) {
        const int row = bm + wm + am * 16 + ly;
#pragma unroll
        for (int an = 0; an < 4; an++) {
            const int col = bn + wn + an * 8 + 2 * lx;
            *(float2*)(C + (size_t)row * N + col)       = make_float2(c[am][an][0], c[am][an][1]);
            *(float2*)(C + (size_t)(row + 8) * N + col) = make_float2(c[am][an][2], c[am][an][3]);
        }
    }
}

// ---------------- deterministic top-K per (b,e) ------------------------------
__global__ __launch_bounds__(256) void topk_kernel() {
    __shared__ unsigned sv[NN];
    __shared__ int red[256];
    __shared__ int cnts[256];
    __shared__ int gtoff[256];
    __shared__ int eqoff[256];
    __shared__ int tot_gt;

    const int be = blockIdx.x;
    const int tid = threadIdx.x;
    const float* g = g_gates + (size_t)be * NN;
    for (int i = tid; i < NN; i += 256) sv[i] = __float_as_uint(g[i]);
    __syncthreads();

    unsigned thr = 0u;
    for (int bit = 30; bit >= 0; bit--) {
        unsigned cand = thr | (1u << bit);
        int c = 0;
        for (int i = tid; i < NN; i += 256) c += (sv[i] >= cand) ? 1 : 0;
        red[tid] = c;
        __syncthreads();
        for (int s = 128; s > 0; s >>= 1) {
            if (tid < s) red[tid] += red[tid + s];
            __syncthreads();
        }
        int tot = red[0];
        __syncthreads();
        if (tot >= KK) thr = cand;
    }

    const int base = tid * (NN / 256);
    int lgt = 0, leq = 0;
#pragma unroll
    for (int j = 0; j < NN / 256; j++) {
        unsigned v = sv[base + j];
        lgt += (v > thr);
        leq += (v == thr);
    }
    red[tid] = lgt;
    cnts[tid] = leq;
    __syncthreads();
    if (tid == 0) {
        int a = 0;
        for (int i = 0; i < 256; i++) { gtoff[i] = a; a += red[i]; }
        tot_gt = a;
        a = 0;
        for (int i = 0; i < 256; i++) { eqoff[i] = a; a += cnts[i]; }
    }
    __syncthreads();

    const int ngt = tot_gt;
    int pgt = gtoff[tid];
    int peq = ngt + eqoff[tid];
    int*   ip = g_idx     + (size_t)be * KK;
    float* gp = g_gateval + (size_t)be * KK;
#pragma unroll
    for (int j = 0; j < NN / 256; j++) {
        unsigned v = sv[base + j];
        if (v > thr) {
            ip[pgt] = base + j;
            gp[pgt] = __uint_as_float(v);
            pgt++;
        } else if (v == thr) {
            if (peq < KK) {
                ip[peq] = base + j;
                gp[peq] = __uint_as_float(v);
            }
            peq++;
        }
    }
}

// ---------------- zero accumulator ------------------------------------------
__global__ void zero_kernel() {
    size_t i = ((size_t)blockIdx.x * blockDim.x + threadIdx.x) * 4;
    if (i < (size_t)BB * NN * DHH) {
        *(float4*)(g_xout + i) = make_float4(0.f, 0.f, 0.f, 0.f);
    }
}

// ---------------- fused gather -> FFN (tf32 mma) -> gated scatter ------------
// block = (token_tile 128, expert, batch), 512 threads, 16 warps (warp 32x32).
#define FS_X 132
#define FS_W 136
#define FFN_XS   (128 * FS_X)
#define FFN_WS   (128 * FS_W)
#define FFN_SMEM_FLOATS (2 * FFN_XS + FFN_WS + 256)
#define FFN_SMEM_BYTES (FFN_SMEM_FLOATS * 4)

__global__ __launch_bounds__(512, 1) void ffn_tf32_kernel(const float* __restrict__ w1r,
                                                          const float* __restrict__ w2r) {
    extern __shared__ float sm[];
    float* Xs = sm;
    float* Hs = sm + FFN_XS;
    float* Ws = sm + 2 * FFN_XS;
    int*   toks = (int*)(sm + 2 * FFN_XS + FFN_WS);
    float* Gs   = sm + 2 * FFN_XS + FFN_WS + 128;

    const int tile = blockIdx.x, e = blockIdx.y, b = blockIdx.z;
    const int tid = threadIdx.x;
    const int be = b * EE + e;
    const int* idxp = g_idx + (size_t)be * KK + tile * 128;
    const float* gvp = g_gateval + (size_t)be * KK + tile * 128;
    const float* w1e = w1r + (size_t)e * DHH * DFF;
    const float* w2e = w2r + (size_t)e * DFF * DHH;

    const int row = tid >> 2, seg = tid & 3;

    {
        float* wd = Ws + row * FS_W + seg * 32;
        const float* wsrc = w1e + (size_t)row * DFF + seg * 32;
#pragma unroll
        for (int j = 0; j < 32; j += 4) cp16(wd + j, wsrc + j);
    }
    CP_COMMIT;

    {
        const int tok = idxp[row];
        if (seg == 0) { toks[row] = tok; Gs[row] = gvp[row]; }
        const float* xr = g_x1 + ((size_t)b * NN + tok) * DHH + seg * 32;
        float* xd = Xs + row * FS_X + seg * 32;
#pragma unroll
        for (int j = 0; j < 32; j += 4) {
            float4 v = *(const float4*)(xr + j);
            xd[j]     = f_rna(v.x);
            xd[j + 1] = f_rna(v.y);
            xd[j + 2] = f_rna(v.z);
            xd[j + 3] = f_rna(v.w);
        }
    }

    const int warp = tid >> 5, lane = tid & 31;
    const int wm = (warp >> 2) * 32, wn = (warp & 3) * 32;
    const int ly = lane >> 2, lx = lane & 3;

    float yacc[2][4][4];
#pragma unroll
    for (int i = 0; i < 2; i++)
#pragma unroll
        for (int j = 0; j < 4; j++)
#pragma unroll
            for (int k = 0; k < 4; k++) yacc[i][j][k] = 0.f;

    for (int c = 0; c < 3; c++) {
        CP_WAIT0;
        __syncthreads();

        float h[2][4][4];
#pragma unroll
        for (int i = 0; i < 2; i++)
#pragma unroll
            for (int j = 0; j < 4; j++)
#pragma unroll
                for (int k = 0; k < 4; k++) h[i][j][k] = 0.f;

#pragma unroll 4
        for (int ks = 0; ks < 16; ks++) {
            const int k0 = ks * 8;
            uint32_t a[2][4], bf[4][2];
#pragma unroll
            for (int am = 0; am < 2; am++) {
                const int off = (wm + am * 16 + ly) * FS_X + k0 + lx;
                a[am][0] = __float_as_uint(Xs[off]);
                a[am][1] = __float_as_uint(Xs[off + 8 * FS_X]);
                a[am][2] = __float_as_uint(Xs[off + 4]);
                a[am][3] = __float_as_uint(Xs[off + 8 * FS_X + 4]);
            }
#pragma unroll
            for (int an = 0; an < 4; an++) {
                const int off = (k0 + lx) * FS_W + wn + an * 8 + ly;
                bf[an][0] = __float_as_uint(Ws[off]);
                bf[an][1] = __float_as_uint(Ws[off + 4 * FS_W]);
            }
#pragma unroll
            for (int am = 0; am < 2; am++)
#pragma unroll
                for (int an = 0; an < 4; an++) mma8(h[am][an], a[am], bf[an]);
        }
        __syncthreads();

        {
            float* wd = Ws + row * FS_W + seg * 32;
            const float* wsrc = w2e + (size_t)(c * 128 + row) * DHH + seg * 32;
#pragma unroll
            for (int j = 0; j < 32; j += 4) cp16(wd + j, wsrc + j);
        }
        CP_COMMIT;

#pragma unroll
        for (int am = 0; am < 2; am++) {
            const int r0 = wm + am * 16 + ly;
#pragma unroll
            for (int an = 0; an < 4; an++) {
                const int col = wn + an * 8 + 2 * lx;
                float v0 = h[am][an][0], v1 = h[am][an][1];
                float v2 = h[am][an][2], v3 = h[am][an][3];
                v0 = v0 / (1.f + expf(-v0));
                v1 = v1 / (1.f + expf(-v1));
                v2 = v2 / (1.f + expf(-v2));
                v3 = v3 / (1.f + expf(-v3));
                *(float2*)&Hs[r0 * FS_X + col]       = make_float2(f_rna(v0), f_rna(v1));
                *(float2*)&Hs[(r0 + 8) * FS_X + col] = make_float2(f_rna(v2), f_rna(v3));
            }
        }
        CP_WAIT0;
        __syncthreads();

#pragma unroll 4
        for (int ks = 0; ks < 16; ks++) {
            const int k0 = ks * 8;
            uint32_t a[2][4], bf[4][2];
#pragma unroll
            for (int am = 0; am < 2; am++) {
                const int off = (wm + am * 16 + ly) * FS_X + k0 + lx;
                a[am][0] = __float_as_uint(Hs[off]);
                a[am][1] = __float_as_uint(Hs[off + 8 * FS_X]);
                a[am][2] = __float_as_uint(Hs[off + 4]);
                a[am][3] = __float_as_uint(Hs[off + 8 * FS_X + 4]);
            }
#pragma unroll
            for (int an = 0; an < 4; an++) {
                const int off = (k0 + lx) * FS_W + wn + an * 8 + ly;
                bf[an][0] = __float_as_uint(Ws[off]);
                bf[an][1] = __float_as_uint(Ws[off + 4 * FS_W]);
            }
#pragma unroll
            for (int am = 0; am < 2; am++)
#pragma unroll
                for (int an = 0; an < 4; an++) mma8(yacc[am][an], a[am], bf[an]);
        }
        __syncthreads();

        if (c < 2) {
            float* wd = Ws + row * FS_W + seg * 32;
            const float* wsrc = w1e + (size_t)row * DFF + (c + 1) * 128 + seg * 32;
#pragma unroll
            for (int j = 0; j < 32; j += 4) cp16(wd + j, wsrc + j);
            CP_COMMIT;
        }
    }

#pragma unroll
    for (int am = 0; am < 2; am++) {
        const int r0 = wm + am * 16 + ly;
        const int tok0 = toks[r0], tok1 = toks[r0 + 8];
        const float g0 = Gs[r0], g1 = Gs[r0 + 8];
        float* o0 = g_xout + ((size_t)b * NN + tok0) * DHH;
        float* o1 = g_xout + ((size_t)b * NN + tok1) * DHH;
#pragma unroll
        for (int an = 0; an < 4; an++) {
            const int col = wn + an * 8 + 2 * lx;
            atomicAdd(o0 + col,     yacc[am][an][0] * g0);
            atomicAdd(o0 + col + 1, yacc[am][an][1] * g0);
            atomicAdd(o1 + col,     yacc[am][an][2] * g1);
            atomicAdd(o1 + col + 1, yacc[am][an][3] * g1);
        }
    }
}

// ---------------- launch ----------------------------------------------------
extern "C" void kernel_launch(void* const* d_in, const int* in_sizes, int n_in,
                              void* d_out, int out_size) {
    const float* x      = (const float*)d_in[0];
    const float* choice = (const float*)d_in[1];
    const float* w1     = (const float*)d_in[2];
    const float* w2     = (const float*)d_in[3];
    const float* head   = (const float*)d_in[4];
    const float* merge  = (const float*)d_in[5];
    float* out = (float*)d_out;

    float *x1p, *xop, *w1r, *w2r, *xr, *hr, *mr, *xorp;
    cudaGetSymbolAddress((void**)&x1p, g_x1);
    cudaGetSymbolAddress((void**)&xop, g_xout);
    cudaGetSymbolAddress((void**)&w1r, g_w1r);
    cudaGetSymbolAddress((void**)&w2r, g_w2r);
    cudaGetSymbolAddress((void**)&xr, g_xr);
    cudaGetSymbolAddress((void**)&hr, g_hr);
    cudaGetSymbolAddress((void**)&mr, g_mr);
    cudaGetSymbolAddress((void**)&xorp, g_xor);

    cudaFuncSetAttribute(gemm_cp_kernel, cudaFuncAttributeMaxDynamicSharedMemorySize,
                         MG_SMEM_BYTES);
    cudaFuncSetAttribute(ffn_tf32_kernel, cudaFuncAttributeMaxDynamicSharedMemorySize,
                         FFN_SMEM_BYTES);
    cudaFuncSetAttribute(logits_softmax_kernel, cudaFuncAttributeMaxDynamicSharedMemorySize,
                         LG_SMEM_BYTES);

    const size_t nX = (size_t)BB * SS * DD;     // 6291456
    const size_t nW = (size_t)DD * DD;          // 589824
    const size_t nW1 = (size_t)EE * DHH * DFF;  // 1179648

    // 0) fused gating matrix W = head_slices @ choice^T (exact fp32)
    choice_proj_kernel<<<DD, 144>>>(head, choice);

    // tf32 pre-rounds
    round_tf32_kernel<<<(unsigned)(nX / 1024), 256>>>(x, xr, nX);
    round_tf32_kernel<<<(unsigned)(nW / 1024), 256>>>(head, hr, nW);
    round_tf32_kernel<<<(unsigned)(nW / 1024), 256>>>(merge, mr, nW);
    round_tf32_kernel<<<(unsigned)(nW1 / 1024), 256>>>(w1, w1r, nW1);
    round_tf32_kernel<<<(unsigned)(nW1 / 1024), 256>>>(w2, w2r, nW1);

    // 1) head projection (tf32 tensor, 64x32 warps, cp.async staging)
    dim3 gproj(DD / 128, (BB * SS) / 128);
    gemm_cp_kernel<<<gproj, 256, MG_SMEM_BYTES>>>(xr, hr, x1p, BB * SS, DD, DD);

    // 2) exact-fp32 logits + softmax (independent of x1 accuracy)
    logits_softmax_kernel<<<(BB * SS) / 64, 384, LG_SMEM_BYTES>>>(x);

    // 3) per-(b,e) top-K
    topk_kernel<<<BB * EE, 256>>>();

    // 4) zero accumulator
    zero_kernel<<<(BB * NN * DHH) / (256 * 4), 256>>>();

    // 5) fused gather -> FFN (tf32 tensor) -> gated scatter
    dim3 gffn(KK / 128, EE, BB);
    ffn_tf32_kernel<<<gffn, 512, FFN_SMEM_BYTES>>>(w1r, w2r);

    // 6) merge projection (round xout, then tf32 tensor GEMM)
    round_tf32_kernel<<<(unsigned)(nX / 1024), 256>>>(xop, xorp, nX);
    gemm_cp_kernel<<<gproj, 256, MG_SMEM_BYTES>>>(xorp, mr, out, BB * SS, DD, DD);
}

// round 14
// speedup vs baseline: 1.0918x; 1.0497x over previous
#include <cuda_runtime.h>
#include <math.h>
#include <stdint.h>

// Problem constants
#define BB  8
#define SS  1024
#define DD  768
#define EE  24
#define DHH 128
#define DFF 384
#define NN  6144          // S*H tokens per batch
#define KK  1024          // tokens per expert
#define HH  6             // heads

// ---------------- scratch (device globals; no allocation allowed) -----------
__device__ float g_x1[(size_t)BB * NN * DHH];     // head-projected tokens
__device__ float g_gates[(size_t)BB * EE * NN];
__device__ int   g_idx[(size_t)BB * EE * KK];
__device__ float g_gateval[(size_t)BB * EE * KK];
__device__ float g_xout[(size_t)BB * NN * DHH];   // scatter accumulator (fp32)
__device__ float g_W[DD * HH * EE];               // fused gating matrix [768][144]
__device__ float g_w1r[(size_t)EE * DHH * DFF];   // w1 rounded to tf32
__device__ float g_w2r[(size_t)EE * DFF * DHH];   // w2 rounded to tf32

// ---------------- helpers ----------------------------------------------------
__device__ __forceinline__ float f_rna(float x) {
    uint32_t u;
    asm("cvt.rna.tf32.f32 %0, %1;" : "=r"(u) : "f"(x));
    return __uint_as_float(u);
}

__device__ __forceinline__ void mma8(float* c, const uint32_t* a, const uint32_t* b) {
    asm volatile(
        "mma.sync.aligned.m16n8k8.row.col.f32.tf32.tf32.f32 "
        "{%0,%1,%2,%3}, {%4,%5,%6,%7}, {%8,%9}, {%0,%1,%2,%3};\n"
        : "+f"(c[0]), "+f"(c[1]), "+f"(c[2]), "+f"(c[3])
        : "r"(a[0]), "r"(a[1]), "r"(a[2]), "r"(a[3]), "r"(b[0]), "r"(b[1]));
}

__device__ __forceinline__ void cp16(void* smem, const void* g) {
    uint32_t s = (uint32_t)__cvta_generic_to_shared(smem);
    asm volatile("cp.async.ca.shared.global [%0], [%1], 16;" :: "r"(s), "l"(g));
}
#define CP_COMMIT asm volatile("cp.async.commit_group;")
#define CP_WAIT0  asm volatile("cp.async.wait_group 0;")

// ---------------- elementwise tf32 round -------------------------------------
__global__ void round_tf32_kernel(const float* __restrict__ src,
                                  float* __restrict__ dst, size_t n) {
    size_t i = ((size_t)blockIdx.x * blockDim.x + threadIdx.x) * 4;
    if (i >= n) return;
    float4 v = *(const float4*)(src + i);
    v.x = f_rna(v.x); v.y = f_rna(v.y); v.z = f_rna(v.z); v.w = f_rna(v.w);
    *(float4*)(dst + i) = v;
}

// ---------------- fused gating matrix: W[d][h*24+e] --------------------------
__global__ __launch_bounds__(144) void choice_proj_kernel(
    const float* __restrict__ head, const float* __restrict__ choice)
{
    __shared__ float hs[DD];
    __shared__ float cs[EE * DHH];
    const int d = blockIdx.x;
    for (int i = threadIdx.x; i < DD; i += 144) hs[i] = head[(size_t)d * DD + i];
    for (int i = threadIdx.x; i < EE * DHH; i += 144) cs[i] = choice[i];
    __syncthreads();
    const int h = threadIdx.x / EE, e = threadIdx.x % EE;
    float a = 0.f;
#pragma unroll 8
    for (int o = 0; o < DHH; o++) a += hs[h * DHH + o] * cs[e * DHH + o];
    g_W[d * (HH * EE) + threadIdx.x] = a;
}

// ---------------- logits (fp32 SIMT GEMM) + softmax --------------------------
#define LG_XS 0
#define LG_WS 2112
#define LG_LS (2112 + 4640)
#define LG_SMEM_BYTES ((2112 + 4640 + 64 * 145) * 4)

__global__ __launch_bounds__(384) void logits_softmax_kernel(const float* __restrict__ x) {
    extern __shared__ float sm[];
    float* Xs = sm + LG_XS;   // [64][33]
    float* Ws = sm + LG_WS;   // [32][145]
    float* Ls = sm + LG_LS;   // [64][145]
    const int tid = threadIdx.x;
    const int row0 = blockIdx.x * 64;
    const int ry = tid / 24, cx = tid % 24;

    float acc[4][6];
#pragma unroll
    for (int i = 0; i < 4; i++)
#pragma unroll
        for (int j = 0; j < 6; j++) acc[i][j] = 0.f;

    for (int k0 = 0; k0 < DD; k0 += 32) {
        for (int i = tid; i < 64 * 32; i += 384) {
            int r = i >> 5, c = i & 31;
            Xs[r * 33 + c] = x[(size_t)(row0 + r) * DD + k0 + c];
        }
        for (int i = tid; i < 32 * 144; i += 384) {
            int r = i / 144, c = i % 144;
            Ws[r * 145 + c] = g_W[(k0 + r) * 144 + c];
        }
        __syncthreads();
#pragma unroll 8
        for (int kk = 0; kk < 32; kk++) {
            float xv[4], wv[6];
#pragma unroll
            for (int i = 0; i < 4; i++) xv[i] = Xs[(ry * 4 + i) * 33 + kk];
#pragma unroll
            for (int j = 0; j < 6; j++) wv[j] = Ws[kk * 145 + cx * 6 + j];
#pragma unroll
            for (int i = 0; i < 4; i++)
#pragma unroll
                for (int j = 0; j < 6; j++) acc[i][j] += xv[i] * wv[j];
        }
        __syncthreads();
    }
#pragma unroll
    for (int i = 0; i < 4; i++)
#pragma unroll
        for (int j = 0; j < 6; j++)
            Ls[(ry * 4 + i) * 145 + cx * 6 + j] = acc[i][j];
    __syncthreads();

    {
        const int r = tid / 6, h = tid % 6;
        const int row = row0 + r;
        const int b = row / SS, s = row % SS;
        const int n = s * HH + h;
        float l[EE];
        float m = -1e30f;
#pragma unroll
        for (int e = 0; e < EE; e++) {
            l[e] = Ls[r * 145 + h * EE + e];
            m = fmaxf(m, l[e]);
        }
        float sum = 0.f;
#pragma unroll
        for (int e = 0; e < EE; e++) { l[e] = expf(l[e] - m); sum += l[e]; }
        const float inv = 1.f / sum;
#pragma unroll
        for (int e = 0; e < EE; e++)
            g_gates[((size_t)(b * EE + e)) * NN + n] = l[e] * inv;
    }
}

// ---------------- single-pass tf32 GEMM (head + merge proj) ------------------
// 128x128 tile, 256 threads, on-the-fly rna rounding in staging, reg-prefetch
// double buffer, 70KB smem -> 2 CTAs/SM.  (R10 champion kernel, unchanged.)
#define SA 36
#define SB 136
#define MG_A (128 * SA)
#define MG_B (32 * SB)
#define MG_BUF (MG_A + MG_B)
#define MG_SMEM_BYTES (2 * MG_BUF * 4)

__global__ __launch_bounds__(256, 2) void gemm1x_kernel(
    const float* __restrict__ A, const float* __restrict__ B,
    float* __restrict__ C, int M, int N, int K)
{
    extern __shared__ float sm[];
    const int tid = threadIdx.x;
    const int bm = blockIdx.y * 128, bn = blockIdx.x * 128;

    const int ar = tid >> 1, ac0 = (tid & 1) * 16;
    const int br = tid >> 3, bc0 = (tid & 7) * 16;

    const int warp = tid >> 5, lane = tid & 31;
    const int wm = (warp >> 2) * 64, wn = (warp & 3) * 32;
    const int ly = lane >> 2, lx = lane & 3;

    const int T = K / 32;

    float4 aR[4], bR[4];
    auto ldg = [&](int kt) {
        const float* as = A + (size_t)(bm + ar) * K + kt * 32 + ac0;
        const float* bs = B + (size_t)(kt * 32 + br) * N + bn + bc0;
#pragma unroll
        for (int j = 0; j < 4; j++) aR[j] = *(const float4*)(as + 4 * j);
#pragma unroll
        for (int j = 0; j < 4; j++) bR[j] = *(const float4*)(bs + 4 * j);
    };
    auto sts = [&](int buf) {
        float* Ad = sm + buf * MG_BUF + ar * SA + ac0;
        float* Bd = sm + buf * MG_BUF + MG_A + br * SB + bc0;
#pragma unroll
        for (int j = 0; j < 4; j++) {
            float4 v = aR[j];
            *(float4*)(Ad + 4 * j) = make_float4(f_rna(v.x), f_rna(v.y), f_rna(v.z), f_rna(v.w));
        }
#pragma unroll
        for (int j = 0; j < 4; j++) {
            float4 v = bR[j];
            *(float4*)(Bd + 4 * j) = make_float4(f_rna(v.x), f_rna(v.y), f_rna(v.z), f_rna(v.w));
        }
    };

    float c[4][4][4];
#pragma unroll
    for (int i = 0; i < 4; i++)
#pragma unroll
        for (int j = 0; j < 4; j++)
#pragma unroll
            for (int k = 0; k < 4; k++) c[i][j][k] = 0.f;

    ldg(0);
    sts(0);
    __syncthreads();

    for (int t = 0; t < T; t++) {
        if (t + 1 < T) ldg(t + 1);
        const float* base = sm + (t & 1) * MG_BUF;
        const float* As = base;
        const float* Bs = base + MG_A;
#pragma unroll
        for (int ks = 0; ks < 4; ks++) {
            const int k0 = ks * 8;
            uint32_t a[4][4], bf[4][2];
#pragma unroll
            for (int am = 0; am < 4; am++) {
                const int off = (wm + am * 16 + ly) * SA + k0 + lx;
                a[am][0] = __float_as_uint(As[off]);
                a[am][1] = __float_as_uint(As[off + 8 * SA]);
                a[am][2] = __float_as_uint(As[off + 4]);
                a[am][3] = __float_as_uint(As[off + 8 * SA + 4]);
            }
#pragma unroll
            for (int an = 0; an < 4; an++) {
                const int off = (k0 + lx) * SB + wn + an * 8 + ly;
                bf[an][0] = __float_as_uint(Bs[off]);
                bf[an][1] = __float_as_uint(Bs[off + 4 * SB]);
            }
#pragma unroll
            for (int am = 0; am < 4; am++)
#pragma unroll
                for (int an = 0; an < 4; an++) mma8(c[am][an], a[am], bf[an]);
        }
        if (t + 1 < T) {
            sts((t + 1) & 1);
            __syncthreads();
        }
    }

#pragma unroll
    for (int am = 0; am < 4; am++) {
        const int row = bm + wm + am * 16 + ly;
#pragma unroll
        for (int an = 0; an < 4; an++) {
            const int col = bn + wn + an * 8 + 2 * lx;
            *(float2*)(C + (size_t)row * N + col)       = make_float2(c[am][an][0], c[am][an][1]);
            *(float2*)(C + (size_t)(row + 8) * N + col) = make_float2(c[am][an][2], c[am][an][3]);
        }
    }
}

// ---------------- deterministic top-K per (b,e): 4-pass radix histogram ------
// Computes the SAME threshold as the 31-pass bit loop (the K-th largest value's
// bits), then the same ordered compaction: strictly-greater tokens in index
// order, then lowest-index ties.
__global__ __launch_bounds__(256) void topk_kernel() {
    __shared__ unsigned sv[NN];        // 24 KB
    __shared__ int ha[257];
    __shared__ int hb[257];
    __shared__ int red[256];
    __shared__ int cnts[256];
    __shared__ int gtoff[256];
    __shared__ int eqoff[256];
    __shared__ int tot_gt;
    __shared__ unsigned s_prefix;
    __shared__ int s_R;

    const int be = blockIdx.x;
    const int tid = threadIdx.x;
    const float* g = g_gates + (size_t)be * NN;
    for (int i = tid; i < NN; i += 256) sv[i] = __float_as_uint(g[i]);
    if (tid == 0) { s_prefix = 0u; s_R = KK; }
    __syncthreads();

    const int base = tid * (NN / 256);

#pragma unroll
    for (int pass = 0; pass < 4; pass++) {
        const int shift = 24 - 8 * pass;
        const unsigned prefix = s_prefix;
        const int R = s_R;
        ha[tid] = 0;
        if (tid == 0) ha[256] = 0;
        __syncthreads();
        // histogram of byte-at-shift among in-group values
#pragma unroll
        for (int j = 0; j < NN / 256; j++) {
            unsigned v = sv[base + j];
            bool ingrp = (pass == 0) ||
                         ((v >> (shift + 8)) == (prefix >> (shift + 8)));
            if (ingrp) atomicAdd(&ha[(v >> shift) & 0xFF], 1);
        }
        __syncthreads();
        // suffix sum: sacc[d] = sum_{b >= d} hist[b]  (Hillis-Steele, 8 steps)
        int* cur = ha;
        int* nxt = hb;
#pragma unroll
        for (int s = 1; s < 256; s <<= 1) {
            int v = cur[tid] + ((tid + s < 256) ? cur[tid + s] : 0);
            nxt[tid] = v;
            if (tid == 0) nxt[256] = 0;
            __syncthreads();
            int* t = cur; cur = nxt; nxt = t;
        }
        // pick digit: largest d with sacc[d] >= R
        if (cur[tid] >= R && cur[tid + 1] < R) {
            s_prefix = prefix | ((unsigned)tid << shift);
            s_R = R - cur[tid + 1];
        }
        __syncthreads();
    }

    const unsigned thr = s_prefix;
    __syncthreads();

    // ---- ordered compaction (identical to previous rounds) ----
    int lgt = 0, leq = 0;
#pragma unroll
    for (int j = 0; j < NN / 256; j++) {
        unsigned v = sv[base + j];
        lgt += (v > thr);
        leq += (v == thr);
    }
    red[tid] = lgt;
    cnts[tid] = leq;
    __syncthreads();
    if (tid == 0) {
        int a = 0;
        for (int i = 0; i < 256; i++) { gtoff[i] = a; a += red[i]; }
        tot_gt = a;
        a = 0;
        for (int i = 0; i < 256; i++) { eqoff[i] = a; a += cnts[i]; }
    }
    __syncthreads();

    const int ngt = tot_gt;
    int pgt = gtoff[tid];
    int peq = ngt + eqoff[tid];
    int*   ip = g_idx     + (size_t)be * KK;
    float* gp = g_gateval + (size_t)be * KK;
#pragma unroll
    for (int j = 0; j < NN / 256; j++) {
        unsigned v = sv[base + j];
        if (v > thr) {
            ip[pgt] = base + j;
            gp[pgt] = __uint_as_float(v);
            pgt++;
        } else if (v == thr) {
            if (peq < KK) {
                ip[peq] = base + j;
                gp[peq] = __uint_as_float(v);
            }
            peq++;
        }
    }
}

// ---------------- zero accumulator ------------------------------------------
__global__ void zero_kernel() {
    size_t i = ((size_t)blockIdx.x * blockDim.x + threadIdx.x) * 4;
    if (i < (size_t)BB * NN * DHH) {
        *(float4*)(g_xout + i) = make_float4(0.f, 0.f, 0.f, 0.f);
    }
}

// ---------------- fused gather -> FFN (tf32 mma) -> gated scatter ------------
// block = (token_tile 128, expert, batch), 512 threads, 16 warps (warp 32x32).
#define FS_X 132
#define FS_W 136
#define FFN_XS   (128 * FS_X)
#define FFN_WS   (128 * FS_W)
#define FFN_SMEM_FLOATS (2 * FFN_XS + FFN_WS + 256)
#define FFN_SMEM_BYTES (FFN_SMEM_FLOATS * 4)

__global__ __launch_bounds__(512, 1) void ffn_tf32_kernel(const float* __restrict__ w1r,
                                                          const float* __restrict__ w2r) {
    extern __shared__ float sm[];
    float* Xs = sm;
    float* Hs = sm + FFN_XS;
    float* Ws = sm + 2 * FFN_XS;
    int*   toks = (int*)(sm + 2 * FFN_XS + FFN_WS);
    float* Gs   = sm + 2 * FFN_XS + FFN_WS + 128;

    const int tile = blockIdx.x, e = blockIdx.y, b = blockIdx.z;
    const int tid = threadIdx.x;
    const int be = b * EE + e;
    const int* idxp = g_idx + (size_t)be * KK + tile * 128;
    const float* gvp = g_gateval + (size_t)be * KK + tile * 128;
    const float* w1e = w1r + (size_t)e * DHH * DFF;
    const float* w2e = w2r + (size_t)e * DFF * DHH;

    const int row = tid >> 2, seg = tid & 3;

    {
        float* wd = Ws + row * FS_W + seg * 32;
        const float* wsrc = w1e + (size_t)row * DFF + seg * 32;
#pragma unroll
        for (int j = 0; j < 32; j += 4) cp16(wd + j, wsrc + j);
    }
    CP_COMMIT;

    {
        const int tok = idxp[row];
        if (seg == 0) { toks[row] = tok; Gs[row] = gvp[row]; }
        const float* xr = g_x1 + ((size_t)b * NN + tok) * DHH + seg * 32;
        float* xd = Xs + row * FS_X + seg * 32;
#pragma unroll
        for (int j = 0; j < 32; j += 4) {
            float4 v = *(const float4*)(xr + j);
            xd[j]     = f_rna(v.x);
            xd[j + 1] = f_rna(v.y);
            xd[j + 2] = f_rna(v.z);
            xd[j + 3] = f_rna(v.w);
        }
    }

    const int warp = tid >> 5, lane = tid & 31;
    const int wm = (warp >> 2) * 32, wn = (warp & 3) * 32;
    const int ly = lane >> 2, lx = lane & 3;

    float yacc[2][4][4];
#pragma unroll
    for (int i = 0; i < 2; i++)
#pragma unroll
        for (int j = 0; j < 4; j++)
#pragma unroll
            for (int k = 0; k < 4; k++) yacc[i][j][k] = 0.f;

    for (int c = 0; c < 3; c++) {
        CP_WAIT0;
        __syncthreads();

        float h[2][4][4];
#pragma unroll
        for (int i = 0; i < 2; i++)
#pragma unroll
            for (int j = 0; j < 4; j++)
#pragma unroll
                for (int k = 0; k < 4; k++) h[i][j][k] = 0.f;

#pragma unroll 4
        for (int ks = 0; ks < 16; ks++) {
            const int k0 = ks * 8;
            uint32_t a[2][4], bf[4][2];
#pragma unroll
            for (int am = 0; am < 2; am++) {
                const int off = (wm + am * 16 + ly) * FS_X + k0 + lx;
                a[am][0] = __float_as_uint(Xs[off]);
                a[am][1] = __float_as_uint(Xs[off + 8 * FS_X]);
                a[am][2] = __float_as_uint(Xs[off + 4]);
                a[am][3] = __float_as_uint(Xs[off + 8 * FS_X + 4]);
            }
#pragma unroll
            for (int an = 0; an < 4; an++) {
                const int off = (k0 + lx) * FS_W + wn + an * 8 + ly;
                bf[an][0] = __float_as_uint(Ws[off]);
                bf[an][1] = __float_as_uint(Ws[off + 4 * FS_W]);
            }
#pragma unroll
            for (int am = 0; am < 2; am++)
#pragma unroll
                for (int an = 0; an < 4; an++) mma8(h[am][an], a[am], bf[an]);
        }
        __syncthreads();

        {
            float* wd = Ws + row * FS_W + seg * 32;
            const float* wsrc = w2e + (size_t)(c * 128 + row) * DHH + seg * 32;
#pragma unroll
            for (int j = 0; j < 32; j += 4) cp16(wd + j, wsrc + j);
        }
        CP_COMMIT;

#pragma unroll
        for (int am = 0; am < 2; am++) {
            const int r0 = wm + am * 16 + ly;
#pragma unroll
            for (int an = 0; an < 4; an++) {
                const int col = wn + an * 8 + 2 * lx;
                float v0 = h[am][an][0], v1 = h[am][an][1];
                float v2 = h[am][an][2], v3 = h[am][an][3];
                v0 = v0 / (1.f + expf(-v0));
                v1 = v1 / (1.f + expf(-v1));
                v2 = v2 / (1.f + expf(-v2));
                v3 = v3 / (1.f + expf(-v3));
                *(float2*)&Hs[r0 * FS_X + col]       = make_float2(f_rna(v0), f_rna(v1));
                *(float2*)&Hs[(r0 + 8) * FS_X + col] = make_float2(f_rna(v2), f_rna(v3));
            }
        }
        CP_WAIT0;
        __syncthreads();

#pragma unroll 4
        for (int ks = 0; ks < 16; ks++) {
            const int k0 = ks * 8;
            uint32_t a[2][4], bf[4][2];
#pragma unroll
            for (int am = 0; am < 2; am++) {
                const int off = (wm + am * 16 + ly) * FS_X + k0 + lx;
                a[am][0] = __float_as_uint(Hs[off]);
                a[am][1] = __float_as_uint(Hs[off + 8 * FS_X]);
                a[am][2] = __float_as_uint(Hs[off + 4]);
                a[am][3] = __float_as_uint(Hs[off + 8 * FS_X + 4]);
            }
#pragma unroll
            for (int an = 0; an < 4; an++) {
                const int off = (k0 + lx) * FS_W + wn + an * 8 + ly;
                bf[an][0] = __float_as_uint(Ws[off]);
                bf[an][1] = __float_as_uint(Ws[off + 4 * FS_W]);
            }
#pragma unroll
            for (int am = 0; am < 2; am++)
#pragma unroll
                for (int an = 0; an < 4; an++) mma8(yacc[am][an], a[am], bf[an]);
        }
        __syncthreads();

        if (c < 2) {
            float* wd = Ws + row * FS_W + seg * 32;
            const float* wsrc = w1e + (size_t)row * DFF + (c + 1) * 128 + seg * 32;
#pragma unroll
            for (int j = 0; j < 32; j += 4) cp16(wd + j, wsrc + j);
            CP_COMMIT;
        }
    }

#pragma unroll
    for (int am = 0; am < 2; am++) {
        const int r0 = wm + am * 16 + ly;
        const int tok0 = toks[r0], tok1 = toks[r0 + 8];
        const float g0 = Gs[r0], g1 = Gs[r0 + 8];
        float* o0 = g_xout + ((size_t)b * NN + tok0) * DHH;
        float* o1 = g_xout + ((size_t)b * NN + tok1) * DHH;
#pragma unroll
        for (int an = 0; an < 4; an++) {
            const int col = wn + an * 8 + 2 * lx;
            atomicAdd(o0 + col,     yacc[am][an][0] * g0);
            atomicAdd(o0 + col + 1, yacc[am][an][1] * g0);
            atomicAdd(o1 + col,     yacc[am][an][2] * g1);
            atomicAdd(o1 + col + 1, yacc[am][an][3] * g1);
        }
    }
}

// ---------------- launch ----------------------------------------------------
extern "C" void kernel_launch(void* const* d_in, const int* in_sizes, int n_in,
                              void* d_out, int out_size) {
    const float* x      = (const float*)d_in[0];
    const float* choice = (const float*)d_in[1];
    const float* w1     = (const float*)d_in[2];
    const float* w2     = (const float*)d_in[3];
    const float* head   = (const float*)d_in[4];
    const float* merge  = (const float*)d_in[5];
    float* out = (float*)d_out;

    float *x1p, *xop, *w1r, *w2r;
    cudaGetSymbolAddress((void**)&x1p, g_x1);
    cudaGetSymbolAddress((void**)&xop, g_xout);
    cudaGetSymbolAddress((void**)&w1r, g_w1r);
    cudaGetSymbolAddress((void**)&w2r, g_w2r);

    cudaFuncSetAttribute(gemm1x_kernel, cudaFuncAttributeMaxDynamicSharedMemorySize,
                         MG_SMEM_BYTES);
    cudaFuncSetAttribute(ffn_tf32_kernel, cudaFuncAttributeMaxDynamicSharedMemorySize,
                         FFN_SMEM_BYTES);
    cudaFuncSetAttribute(logits_softmax_kernel, cudaFuncAttributeMaxDynamicSharedMemorySize,
                         LG_SMEM_BYTES);

    const size_t nW1 = (size_t)EE * DHH * DFF;  // 1179648

    // 0) fused gating matrix W = head_slices @ choice^T (exact fp32)
    choice_proj_kernel<<<DD, 144>>>(head, choice);

    // tf32 rounds for expert weights
    round_tf32_kernel<<<(unsigned)(nW1 / 1024), 256>>>(w1, w1r, nW1);
    round_tf32_kernel<<<(unsigned)(nW1 / 1024), 256>>>(w2, w2r, nW1);

    // 1) head projection (single-pass tf32, inline rounding)
    dim3 gproj(DD / 128, (BB * SS) / 128);
    gemm1x_kernel<<<gproj, 256, MG_SMEM_BYTES>>>(x, head, x1p, BB * SS, DD, DD);

    // 2) exact-fp32 logits + softmax (independent of x1 accuracy)
    logits_softmax_kernel<<<(BB * SS) / 64, 384, LG_SMEM_BYTES>>>(x);

    // 3) per-(b,e) top-K (4-pass radix histogram)
    topk_kernel<<<BB * EE, 256>>>();

    // 4) zero accumulator
    zero_kernel<<<(BB * NN * DHH) / (256 * 4), 256>>>();

    // 5) fused gather -> FFN (tf32 tensor) -> gated scatter
    dim3 gffn(KK / 128, EE, BB);
    ffn_tf32_kernel<<<gffn, 512, FFN_SMEM_BYTES>>>(w1r, w2r);

    // 6) merge projection (single-pass tf32, inline rounding)
    gemm1x_kernel<<<gproj, 256, MG_SMEM_BYTES>>>(xop, merge, out,
                                                 BB * SS, DD, DD);
}

// round 16
// speedup vs baseline: 1.2759x; 1.1686x over previous
#include <cuda_runtime.h>
#include <math.h>
#include <stdint.h>

// Problem constants
#define BB  8
#define SS  1024
#define DD  768
#define EE  24
#define DHH 128
#define DFF 384
#define NN  6144          // S*H tokens per batch
#define KK  1024          // tokens per expert
#define HH  6             // heads

// ---------------- scratch (device globals; no allocation allowed) -----------
__device__ float g_x1[(size_t)BB * NN * DHH];     // head-projected tokens
__device__ float g_gates[(size_t)BB * EE * NN];
__device__ int   g_idx[(size_t)BB * EE * KK];
__device__ float g_gateval[(size_t)BB * EE * KK];
__device__ float g_xout[(size_t)BB * NN * DHH];   // scatter accumulator (fp32)
__device__ float g_W[DD * HH * EE];               // fused gating matrix [768][144]
__device__ float g_w1r[(size_t)EE * DHH * DFF];   // w1 rounded to tf32
__device__ float g_w2r[(size_t)EE * DFF * DHH];   // w2 rounded to tf32

// ---------------- helpers ----------------------------------------------------
__device__ __forceinline__ float f_rna(float x) {
    uint32_t u;
    asm("cvt.rna.tf32.f32 %0, %1;" : "=r"(u) : "f"(x));
    return __uint_as_float(u);
}

__device__ __forceinline__ void mma8(float* c, const uint32_t* a, const uint32_t* b) {
    asm volatile(
        "mma.sync.aligned.m16n8k8.row.col.f32.tf32.tf32.f32 "
        "{%0,%1,%2,%3}, {%4,%5,%6,%7}, {%8,%9}, {%0,%1,%2,%3};\n"
        : "+f"(c[0]), "+f"(c[1]), "+f"(c[2]), "+f"(c[3])
        : "r"(a[0]), "r"(a[1]), "r"(a[2]), "r"(a[3]), "r"(b[0]), "r"(b[1]));
}

__device__ __forceinline__ void cp16(void* smem, const void* g) {
    uint32_t s = (uint32_t)__cvta_generic_to_shared(smem);
    asm volatile("cp.async.ca.shared.global [%0], [%1], 16;" :: "r"(s), "l"(g));
}
#define CP_COMMIT asm volatile("cp.async.commit_group;")

// ---------------- prep: round w1/w2 to tf32 + zero xout (one launch) ---------
// blocks [0,1152): w1 round; [1152,2304): w2 round; [2304,8448): zero xout
__global__ void prep_kernel(const float* __restrict__ w1,
                            const float* __restrict__ w2) {
    const unsigned b = blockIdx.x;
    const int t = threadIdx.x;
    if (b < 1152u) {
        size_t i = ((size_t)b * 256 + t) * 4;
        float4 v = *(const float4*)(w1 + i);
        v.x = f_rna(v.x); v.y = f_rna(v.y); v.z = f_rna(v.z); v.w = f_rna(v.w);
        *(float4*)(g_w1r + i) = v;
    } else if (b < 2304u) {
        size_t i = ((size_t)(b - 1152u) * 256 + t) * 4;
        float4 v = *(const float4*)(w2 + i);
        v.x = f_rna(v.x); v.y = f_rna(v.y); v.z = f_rna(v.z); v.w = f_rna(v.w);
        *(float4*)(g_w2r + i) = v;
    } else {
        size_t i = ((size_t)(b - 2304u) * 256 + t) * 4;
        *(float4*)(g_xout + i) = make_float4(0.f, 0.f, 0.f, 0.f);
    }
}

// ---------------- fused gating matrix: W[d][h*24+e] --------------------------
__global__ __launch_bounds__(144) void choice_proj_kernel(
    const float* __restrict__ head, const float* __restrict__ choice)
{
    __shared__ float hs[DD];
    __shared__ float cs[EE * DHH];
    const int d = blockIdx.x;
    for (int i = threadIdx.x; i < DD; i += 144) hs[i] = head[(size_t)d * DD + i];
    for (int i = threadIdx.x; i < EE * DHH; i += 144) cs[i] = choice[i];
    __syncthreads();
    const int h = threadIdx.x / EE, e = threadIdx.x % EE;
    float a = 0.f;
#pragma unroll 8
    for (int o = 0; o < DHH; o++) a += hs[h * DHH + o] * cs[e * DHH + o];
    g_W[d * (HH * EE) + threadIdx.x] = a;
}

// ---------------- logits (fp32 SIMT GEMM) + softmax --------------------------
#define LG_XS 0
#define LG_WS 2112
#define LG_LS (2112 + 4640)
#define LG_SMEM_BYTES ((2112 + 4640 + 64 * 145) * 4)

__global__ __launch_bounds__(384) void logits_softmax_kernel(const float* __restrict__ x) {
    extern __shared__ float sm[];
    float* Xs = sm + LG_XS;   // [64][33]
    float* Ws = sm + LG_WS;   // [32][145]
    float* Ls = sm + LG_LS;   // [64][145]
    const int tid = threadIdx.x;
    const int row0 = blockIdx.x * 64;
    const int ry = tid / 24, cx = tid % 24;

    float acc[4][6];
#pragma unroll
    for (int i = 0; i < 4; i++)
#pragma unroll
        for (int j = 0; j < 6; j++) acc[i][j] = 0.f;

    for (int k0 = 0; k0 < DD; k0 += 32) {
        for (int i = tid; i < 64 * 32; i += 384) {
            int r = i >> 5, c = i & 31;
            Xs[r * 33 + c] = x[(size_t)(row0 + r) * DD + k0 + c];
        }
        for (int i = tid; i < 32 * 144; i += 384) {
            int r = i / 144, c = i % 144;
            Ws[r * 145 + c] = g_W[(k0 + r) * 144 + c];
        }
        __syncthreads();
#pragma unroll 8
        for (int kk = 0; kk < 32; kk++) {
            float xv[4], wv[6];
#pragma unroll
            for (int i = 0; i < 4; i++) xv[i] = Xs[(ry * 4 + i) * 33 + kk];
#pragma unroll
            for (int j = 0; j < 6; j++) wv[j] = Ws[kk * 145 + cx * 6 + j];
#pragma unroll
            for (int i = 0; i < 4; i++)
#pragma unroll
                for (int j = 0; j < 6; j++) acc[i][j] += xv[i] * wv[j];
        }
        __syncthreads();
    }
#pragma unroll
    for (int i = 0; i < 4; i++)
#pragma unroll
        for (int j = 0; j < 6; j++)
            Ls[(ry * 4 + i) * 145 + cx * 6 + j] = acc[i][j];
    __syncthreads();

    {
        const int r = tid / 6, h = tid % 6;
        const int row = row0 + r;
        const int b = row / SS, s = row % SS;
        const int n = s * HH + h;
        float l[EE];
        float m = -1e30f;
#pragma unroll
        for (int e = 0; e < EE; e++) {
            l[e] = Ls[r * 145 + h * EE + e];
            m = fmaxf(m, l[e]);
        }
        float sum = 0.f;
#pragma unroll
        for (int e = 0; e < EE; e++) { l[e] = expf(l[e] - m); sum += l[e]; }
        const float inv = 1.f / sum;
#pragma unroll
        for (int e = 0; e < EE; e++)
            g_gates[((size_t)(b * EE + e)) * NN + n] = l[e] * inv;
    }
}

// ---------------- single-pass tf32 GEMM (head + merge proj) ------------------
// 128x128 tile, 256 threads, inline rna rounding, reg-prefetch double buffer,
// 70KB smem -> 2 CTAs/SM.  (R10/R14 champion kernel, unchanged.)
#define SA 36
#define SB 136
#define MG_A (128 * SA)
#define MG_B (32 * SB)
#define MG_BUF (MG_A + MG_B)
#define MG_SMEM_BYTES (2 * MG_BUF * 4)

__global__ __launch_bounds__(256, 2) void gemm1x_kernel(
    const float* __restrict__ A, const float* __restrict__ B,
    float* __restrict__ C, int M, int N, int K)
{
    extern __shared__ float sm[];
    const int tid = threadIdx.x;
    const int bm = blockIdx.y * 128, bn = blockIdx.x * 128;

    const int ar = tid >> 1, ac0 = (tid & 1) * 16;
    const int br = tid >> 3, bc0 = (tid & 7) * 16;

    const int warp = tid >> 5, lane = tid & 31;
    const int wm = (warp >> 2) * 64, wn = (warp & 3) * 32;
    const int ly = lane >> 2, lx = lane & 3;

    const int T = K / 32;

    float4 aR[4], bR[4];
    auto ldg = [&](int kt) {
        const float* as = A + (size_t)(bm + ar) * K + kt * 32 + ac0;
        const float* bs = B + (size_t)(kt * 32 + br) * N + bn + bc0;
#pragma unroll
        for (int j = 0; j < 4; j++) aR[j] = *(const float4*)(as + 4 * j);
#pragma unroll
        for (int j = 0; j < 4; j++) bR[j] = *(const float4*)(bs + 4 * j);
    };
    auto sts = [&](int buf) {
        float* Ad = sm + buf * MG_BUF + ar * SA + ac0;
        float* Bd = sm + buf * MG_BUF + MG_A + br * SB + bc0;
#pragma unroll
        for (int j = 0; j < 4; j++) {
            float4 v = aR[j];
            *(float4*)(Ad + 4 * j) = make_float4(f_rna(v.x), f_rna(v.y), f_rna(v.z), f_rna(v.w));
        }
#pragma unroll
        for (int j = 0; j < 4; j++) {
            float4 v = bR[j];
            *(float4*)(Bd + 4 * j) = make_float4(f_rna(v.x), f_rna(v.y), f_rna(v.z), f_rna(v.w));
        }
    };

    float c[4][4][4];
#pragma unroll
    for (int i = 0; i < 4; i++)
#pragma unroll
        for (int j = 0; j < 4; j++)
#pragma unroll
            for (int k = 0; k < 4; k++) c[i][j][k] = 0.f;

    ldg(0);
    sts(0);
    __syncthreads();

    for (int t = 0; t < T; t++) {
        if (t + 1 < T) ldg(t + 1);
        const float* base = sm + (t & 1) * MG_BUF;
        const float* As = base;
        const float* Bs = base + MG_A;
#pragma unroll
        for (int ks = 0; ks < 4; ks++) {
            const int k0 = ks * 8;
            uint32_t a[4][4], bf[4][2];
#pragma unroll
            for (int am = 0; am < 4; am++) {
                const int off = (wm + am * 16 + ly) * SA + k0 + lx;
                a[am][0] = __float_as_uint(As[off]);
                a[am][1] = __float_as_uint(As[off + 8 * SA]);
                a[am][2] = __float_as_uint(As[off + 4]);
                a[am][3] = __float_as_uint(As[off + 8 * SA + 4]);
            }
#pragma unroll
            for (int an = 0; an < 4; an++) {
                const int off = (k0 + lx) * SB + wn + an * 8 + ly;
                bf[an][0] = __float_as_uint(Bs[off]);
                bf[an][1] = __float_as_uint(Bs[off + 4 * SB]);
            }
#pragma unroll
            for (int am = 0; am < 4; am++)
#pragma unroll
                for (int an = 0; an < 4; an++) mma8(c[am][an], a[am], bf[an]);
        }
        if (t + 1 < T) {
            sts((t + 1) & 1);
            __syncthreads();
        }
    }

#pragma unroll
    for (int am = 0; am < 4; am++) {
        const int row = bm + wm + am * 16 + ly;
#pragma unroll
        for (int an = 0; an < 4; an++) {
            const int col = bn + wn + an * 8 + 2 * lx;
            *(float2*)(C + (size_t)row * N + col)       = make_float2(c[am][an][0], c[am][an][1]);
            *(float2*)(C + (size_t)(row + 8) * N + col) = make_float2(c[am][an][2], c[am][an][3]);
        }
    }
}

// ---------------- deterministic top-K per (b,e): 4-pass radix histogram ------
__global__ __launch_bounds__(256) void topk_kernel() {
    __shared__ unsigned sv[NN];
    __shared__ int ha[257];
    __shared__ int hb[257];
    __shared__ int red[256];
    __shared__ int cnts[256];
    __shared__ int gtoff[256];
    __shared__ int eqoff[256];
    __shared__ int tot_gt;
    __shared__ unsigned s_prefix;
    __shared__ int s_R;

    const int be = blockIdx.x;
    const int tid = threadIdx.x;
    const float* g = g_gates + (size_t)be * NN;
    for (int i = tid; i < NN; i += 256) sv[i] = __float_as_uint(g[i]);
    if (tid == 0) { s_prefix = 0u; s_R = KK; }
    __syncthreads();

    const int base = tid * (NN / 256);

#pragma unroll
    for (int pass = 0; pass < 4; pass++) {
        const int shift = 24 - 8 * pass;
        const unsigned prefix = s_prefix;
        const int R = s_R;
        ha[tid] = 0;
        if (tid == 0) ha[256] = 0;
        __syncthreads();
#pragma unroll
        for (int j = 0; j < NN / 256; j++) {
            unsigned v = sv[base + j];
            bool ingrp = (pass == 0) ||
                         ((v >> (shift + 8)) == (prefix >> (shift + 8)));
            if (ingrp) atomicAdd(&ha[(v >> shift) & 0xFF], 1);
        }
        __syncthreads();
        int* cur = ha;
        int* nxt = hb;
#pragma unroll
        for (int s = 1; s < 256; s <<= 1) {
            int v = cur[tid] + ((tid + s < 256) ? cur[tid + s] : 0);
            nxt[tid] = v;
            if (tid == 0) nxt[256] = 0;
            __syncthreads();
            int* t = cur; cur = nxt; nxt = t;
        }
        if (cur[tid] >= R && cur[tid + 1] < R) {
            s_prefix = prefix | ((unsigned)tid << shift);
            s_R = R - cur[tid + 1];
        }
        __syncthreads();
    }

    const unsigned thr = s_prefix;
    __syncthreads();

    int lgt = 0, leq = 0;
#pragma unroll
    for (int j = 0; j < NN / 256; j++) {
        unsigned v = sv[base + j];
        lgt += (v > thr);
        leq += (v == thr);
    }
    red[tid] = lgt;
    cnts[tid] = leq;
    __syncthreads();
    if (tid == 0) {
        int a = 0;
        for (int i = 0; i < 256; i++) { gtoff[i] = a; a += red[i]; }
        tot_gt = a;
        a = 0;
        for (int i = 0; i < 256; i++) { eqoff[i] = a; a += cnts[i]; }
    }
    __syncthreads();

    const int ngt = tot_gt;
    int pgt = gtoff[tid];
    int peq = ngt + eqoff[tid];
    int*   ip = g_idx     + (size_t)be * KK;
    float* gp = g_gateval + (size_t)be * KK;
#pragma unroll
    for (int j = 0; j < NN / 256; j++) {
        unsigned v = sv[base + j];
        if (v > thr) {
            ip[pgt] = base + j;
            gp[pgt] = __uint_as_float(v);
            pgt++;
        } else if (v == thr) {
            if (peq < KK) {
                ip[peq] = base + j;
                gp[peq] = __uint_as_float(v);
            }
            peq++;
        }
    }
}

// ---------------- fused gather -> FFN (tf32 mma) -> gated scatter ------------
// block = (token_tile 128, expert, batch), 512 threads, 16 warps (warp 32x32).
// W streamed through a 5-slot ring of 32-row slices (cp.async, per-slice
// wait_group + __syncthreads barrier before reading cross-thread staged data).
// 6 phases: q=2c -> X@W1c, q=2c+1 -> H@W2c. Slot(q,s) = (4q+s)%5; phase q's
// slice0 committed mid-mainloop of q-1, slices 1..3 after q-1's end sync.
#define FS_X 132
#define FS_W 136
#define FFN_XS (128 * FS_X)
#define WSL (32 * FS_W)         // 4352 floats per W slice
#define NSLOT 5
#define FFN_SMEM_FLOATS (2 * FFN_XS + NSLOT * WSL + 256)
#define FFN_SMEM_BYTES (FFN_SMEM_FLOATS * 4)

__global__ __launch_bounds__(512, 1) void ffn_tf32_kernel(const float* __restrict__ w1r,
                                                          const float* __restrict__ w2r) {
    extern __shared__ float sm[];
    float* Xs = sm;
    float* Hs = sm + FFN_XS;
    float* Wr = sm + 2 * FFN_XS;
    int*   toks = (int*)(sm + 2 * FFN_XS + NSLOT * WSL);
    float* Gs   = sm + 2 * FFN_XS + NSLOT * WSL + 128;

    const int tile = blockIdx.x, e = blockIdx.y, b = blockIdx.z;
    const int tid = threadIdx.x;
    const int be = b * EE + e;
    const int* idxp = g_idx + (size_t)be * KK + tile * 128;
    const float* gvp = g_gateval + (size_t)be * KK + tile * 128;
    const float* w1e = w1r + (size_t)e * DHH * DFF;
    const float* w2e = w2r + (size_t)e * DFF * DHH;

    // staging coords: 512 threads cover 32 rows x 128 cols (8 floats/thread)
    const int sr = tid >> 4, sc0 = (tid & 15) * 8;
    // gather coords
    const int row = tid >> 2, seg = tid & 3;

    auto stageW = [&](int q, int s) {
        const int slot = (4 * q + s) % NSLOT;
        float* wd = Wr + slot * WSL + sr * FS_W + sc0;
        const int c = q >> 1;
        const float* src;
        if ((q & 1) == 0) src = w1e + (size_t)(s * 32 + sr) * DFF + c * 128 + sc0;
        else              src = w2e + (size_t)(c * 128 + s * 32 + sr) * DHH + sc0;
        cp16(wd, src);
        cp16(wd + 4, src + 4);
    };

    auto waitg = [&](int n) {
        switch (n) {
            case 0: asm volatile("cp.async.wait_group 0;"); break;
            case 1: asm volatile("cp.async.wait_group 1;"); break;
            case 2: asm volatile("cp.async.wait_group 2;"); break;
            default: asm volatile("cp.async.wait_group 3;"); break;
        }
    };

    // prologue: stage phase 0 slices 0..3 (4 groups)
#pragma unroll
    for (int s = 0; s < 4; s++) { stageW(0, s); CP_COMMIT; }

    // gather X into Xs (tf32-rounded); overlaps with W loads
    {
        const int tok = idxp[row];
        if (seg == 0) { toks[row] = tok; Gs[row] = gvp[row]; }
        const float* xr = g_x1 + ((size_t)b * NN + tok) * DHH + seg * 32;
        float* xd = Xs + row * FS_X + seg * 32;
#pragma unroll
        for (int j = 0; j < 32; j += 4) {
            float4 v = *(const float4*)(xr + j);
            xd[j]     = f_rna(v.x);
            xd[j + 1] = f_rna(v.y);
            xd[j + 2] = f_rna(v.z);
            xd[j + 3] = f_rna(v.w);
        }
    }
    __syncthreads();

    const int warp = tid >> 5, lane = tid & 31;
    const int wm = (warp >> 2) * 32, wn = (warp & 3) * 32;
    const int ly = lane >> 2, lx = lane & 3;

    auto run_phase = [&](int q, const float* Asm, float acc[2][4][4]) {
        for (int s = 0; s < 4; s++) {
            int w;
            if (q < 5) w = (s <= 1) ? 3 : (s == 2) ? 2 : 1;
            else       w = (s == 0) ? 3 : (s == 1) ? 2 : (s == 2) ? 1 : 0;
            waitg(w);
            __syncthreads();   // cross-thread visibility of the staged slice
            const float* Wb = Wr + ((4 * q + s) % NSLOT) * WSL;
#pragma unroll
            for (int ksl = 0; ksl < 4; ksl++) {
                const int k0 = (s * 4 + ksl) * 8;
                uint32_t a[2][4], bf[4][2];
#pragma unroll
                for (int am = 0; am < 2; am++) {
                    const int off = (wm + am * 16 + ly) * FS_X + k0 + lx;
                    a[am][0] = __float_as_uint(Asm[off]);
                    a[am][1] = __float_as_uint(Asm[off + 8 * FS_X]);
                    a[am][2] = __float_as_uint(Asm[off + 4]);
                    a[am][3] = __float_as_uint(Asm[off + 8 * FS_X + 4]);
                }
#pragma unroll
                for (int an = 0; an < 4; an++) {
                    const int off = (ksl * 8 + lx) * FS_W + wn + an * 8 + ly;
                    bf[an][0] = __float_as_uint(Wb[off]);
                    bf[an][1] = __float_as_uint(Wb[off + 4 * FS_W]);
                }
#pragma unroll
                for (int am = 0; am < 2; am++)
#pragma unroll
                    for (int an = 0; an < 4; an++) mma8(acc[am][an], a[am], bf[an]);
            }
            if (s == 0 && q < 5) { stageW(q + 1, 0); CP_COMMIT; }
        }
    };

    float yacc[2][4][4];
#pragma unroll
    for (int i = 0; i < 2; i++)
#pragma unroll
        for (int j = 0; j < 4; j++)
#pragma unroll
            for (int k = 0; k < 4; k++) yacc[i][j][k] = 0.f;

    for (int c = 0; c < 3; c++) {
        const int q1 = 2 * c, q2 = 2 * c + 1;

        float h[2][4][4];
#pragma unroll
        for (int i = 0; i < 2; i++)
#pragma unroll
            for (int j = 0; j < 4; j++)
#pragma unroll
                for (int k = 0; k < 4; k++) h[i][j][k] = 0.f;

        // ---- gemm1: H = X @ W1c ----
        run_phase(q1, Xs, h);
        __syncthreads();
        { stageW(q1 + 1, 1); CP_COMMIT; stageW(q1 + 1, 2); CP_COMMIT;
          stageW(q1 + 1, 3); CP_COMMIT; }

        // silu -> Hs (tf32-rounded); overlaps W2 slice loads
#pragma unroll
        for (int am = 0; am < 2; am++) {
            const int r0 = wm + am * 16 + ly;
#pragma unroll
            for (int an = 0; an < 4; an++) {
                const int col = wn + an * 8 + 2 * lx;
                float v0 = h[am][an][0], v1 = h[am][an][1];
                float v2 = h[am][an][2], v3 = h[am][an][3];
                v0 = v0 / (1.f + expf(-v0));
                v1 = v1 / (1.f + expf(-v1));
                v2 = v2 / (1.f + expf(-v2));
                v3 = v3 / (1.f + expf(-v3));
                *(float2*)&Hs[r0 * FS_X + col]       = make_float2(f_rna(v0), f_rna(v1));
                *(float2*)&Hs[(r0 + 8) * FS_X + col] = make_float2(f_rna(v2), f_rna(v3));
            }
        }
        __syncthreads();

        // ---- gemm2: Y += H @ W2c ----
        run_phase(q2, Hs, yacc);
        __syncthreads();
        if (q2 < 5) { stageW(q2 + 1, 1); CP_COMMIT; stageW(q2 + 1, 2); CP_COMMIT;
                      stageW(q2 + 1, 3); CP_COMMIT; }
    }

    // gated scatter-add
#pragma unroll
    for (int am = 0; am < 2; am++) {
        const int r0 = wm + am * 16 + ly;
        const int tok0 = toks[r0], tok1 = toks[r0 + 8];
        const float g0 = Gs[r0], g1 = Gs[r0 + 8];
        float* o0 = g_xout + ((size_t)b * NN + tok0) * DHH;
        float* o1 = g_xout + ((size_t)b * NN + tok1) * DHH;
#pragma unroll
        for (int an = 0; an < 4; an++) {
            const int col = wn + an * 8 + 2 * lx;
            atomicAdd(o0 + col,     yacc[am][an][0] * g0);
            atomicAdd(o0 + col + 1, yacc[am][an][1] * g0);
            atomicAdd(o1 + col,     yacc[am][an][2] * g1);
            atomicAdd(o1 + col + 1, yacc[am][an][3] * g1);
        }
    }
}

// ---------------- launch ----------------------------------------------------
extern "C" void kernel_launch(void* const* d_in, const int* in_sizes, int n_in,
                              void* d_out, int out_size) {
    const float* x      = (const float*)d_in[0];
    const float* choice = (const float*)d_in[1];
    const float* w1     = (const float*)d_in[2];
    const float* w2     = (const float*)d_in[3];
    const float* head   = (const float*)d_in[4];
    const float* merge  = (const float*)d_in[5];
    float* out = (float*)d_out;

    float *x1p, *xop, *w1r, *w2r;
    cudaGetSymbolAddress((void**)&x1p, g_x1);
    cudaGetSymbolAddress((void**)&xop, g_xout);
    cudaGetSymbolAddress((void**)&w1r, g_w1r);
    cudaGetSymbolAddress((void**)&w2r, g_w2r);

    cudaFuncSetAttribute(gemm1x_kernel, cudaFuncAttributeMaxDynamicSharedMemorySize,
                         MG_SMEM_BYTES);
    cudaFuncSetAttribute(ffn_tf32_kernel, cudaFuncAttributeMaxDynamicSharedMemorySize,
                         FFN_SMEM_BYTES);
    cudaFuncSetAttribute(logits_softmax_kernel, cudaFuncAttributeMaxDynamicSharedMemorySize,
                         LG_SMEM_BYTES);

    // 1) prep: round w1/w2 to tf32 + zero scatter accumulator
    prep_kernel<<<8448, 256>>>(w1, w2);

    // 2) fused gating matrix W = head_slices @ choice^T (exact fp32)
    choice_proj_kernel<<<DD, 144>>>(head, choice);

    // 3) head projection (single-pass tf32, inline rounding)
    dim3 gproj(DD / 128, (BB * SS) / 128);
    gemm1x_kernel<<<gproj, 256, MG_SMEM_BYTES>>>(x, head, x1p, BB * SS, DD, DD);

    // 4) exact-fp32 logits + softmax
    logits_softmax_kernel<<<(BB * SS) / 64, 384, LG_SMEM_BYTES>>>(x);

    // 5) per-(b,e) top-K (4-pass radix histogram)
    topk_kernel<<<BB * EE, 256>>>();

    // 6) fused gather -> FFN (tf32 tensor, W-ring pipeline) -> gated scatter
    dim3 gffn(KK / 128, EE, BB);
    ffn_tf32_kernel<<<gffn, 512, FFN_SMEM_BYTES>>>(w1r, w2r);

    // 7) merge projection (single-pass tf32, inline rounding)
    gemm1x_kernel<<<gproj, 256, MG_SMEM_BYTES>>>(xop, merge, out,
                                                 BB * SS, DD, DD);
}